// round 8
// baseline (speedup 1.0000x reference)
#include <cuda_runtime.h>
#include <cuda_bf16.h>
#include <cstdint>
#include <cstddef>

// ---------------------------------------------------------------------------
// GraphConvolution (base sm_103: mma.sync HMMA path, no tcgen05):
//   e     = H_e @ p^T
//   M1    = (T*diag(e)) @ T^T        symmetric -> lower-tri 256x128 tiles
//   Bcomb = 0.5*(M1'+1) .* adj_v     fused into gemm1 epilogue, bf16 hi/lo
//   Y     = Bcomb @ H_v              bf16-split mma -> Y hi/lo
//   ret   = Y @ W + bias             bf16-split mma
//   out   = concat(ret, H_e)
// ---------------------------------------------------------------------------

#define N_NODES 4096
#define E_EDGES 8192
#define IN_V    512
#define OUT_V   512
#define IN_E    128
#define KC      64
#define NCHUNK1 (E_EDGES / KC)    // 128
#define NCHUNK2 (N_NODES / KC)    // 64
#define NCHUNK3 (IN_V / KC)       // 8

// gemm1: 256x128 tiles over lower triangle: ct <= 2*rt+1, rt in [0,16)
#define NBAND   16
#define NTILE1  272               // sum_{rt} (2rt+2)

// gemm1 smem: stage = Ahi(32K)+Alo(32K)+Bhi(16K)+Blo(16K) = 96KB, 2 stages
#define G1_STAGE  98304
#define G1_SMEM   (2 * G1_STAGE)
// gemm2/3 smem: 64KB stage x 3
#define STAGE_BYTES 65536
#define NSTAGE      3
#define GEMM_SMEM   (NSTAGE * STAGE_BYTES)

// Static device scratch
__device__ float g_escale[E_EDGES];
__device__ __nv_bfloat16 g_Ghi[(size_t)N_NODES * E_EDGES];
__device__ __nv_bfloat16 g_Glo[(size_t)N_NODES * E_EDGES];
__device__ __nv_bfloat16 g_Thi[(size_t)N_NODES * E_EDGES];
__device__ __nv_bfloat16 g_Tlo[(size_t)N_NODES * E_EDGES];
__device__ __nv_bfloat16 g_Bhi[(size_t)N_NODES * N_NODES];
__device__ __nv_bfloat16 g_Blo[(size_t)N_NODES * N_NODES];
__device__ __nv_bfloat16 g_HvThi[(size_t)IN_V * N_NODES];
__device__ __nv_bfloat16 g_HvTlo[(size_t)IN_V * N_NODES];
__device__ __nv_bfloat16 g_Yhi[(size_t)N_NODES * IN_V];
__device__ __nv_bfloat16 g_Ylo[(size_t)N_NODES * IN_V];
__device__ __nv_bfloat16 g_WThi[(size_t)OUT_V * IN_V];
__device__ __nv_bfloat16 g_WTlo[(size_t)OUT_V * IN_V];

// ------------------------------ helpers ------------------------------------
__device__ __forceinline__ uint32_t smem_u32(const void* p) {
    uint32_t a;
    asm("{ .reg .u64 t; cvta.to.shared.u64 t, %1; cvt.u32.u64 %0, t; }"
        : "=r"(a) : "l"(p));
    return a;
}
__device__ __forceinline__ uint32_t swz(uint32_t x) { return x ^ ((x >> 3) & 0x70u); }

__device__ __forceinline__ void ldsm_x4(uint32_t& a0, uint32_t& a1,
                                        uint32_t& a2, uint32_t& a3, uint32_t addr) {
    asm volatile("ldmatrix.sync.aligned.m8n8.x4.shared.b16 {%0,%1,%2,%3}, [%4];"
                 : "=r"(a0), "=r"(a1), "=r"(a2), "=r"(a3) : "r"(addr));
}
__device__ __forceinline__ void mma_bf16(float* d, const uint32_t* a, const uint32_t* b) {
    asm volatile(
        "mma.sync.aligned.m16n8k16.row.col.f32.bf16.bf16.f32 "
        "{%0,%1,%2,%3}, {%4,%5,%6,%7}, {%8,%9}, {%0,%1,%2,%3};"
        : "+f"(d[0]), "+f"(d[1]), "+f"(d[2]), "+f"(d[3])
        : "r"(a[0]), "r"(a[1]), "r"(a[2]), "r"(a[3]), "r"(b[0]), "r"(b[1]));
}
__device__ __forceinline__ void bsplit(float v, __nv_bfloat16& h, __nv_bfloat16& l) {
    h = __float2bfloat16(v);
    l = __float2bfloat16(v - __bfloat162float(h));
}
__device__ __forceinline__ void cpa16(uint32_t dst, const void* src) {
    asm volatile("cp.async.cg.shared.global [%0], [%1], 16;" :: "r"(dst), "l"(src));
}
#define CP_COMMIT() asm volatile("cp.async.commit_group;" ::: "memory")
#define CP_WAIT0()  asm volatile("cp.async.wait_group 0;" ::: "memory")
#define CP_WAIT1()  asm volatile("cp.async.wait_group 1;" ::: "memory")

// ---------------------------------------------------------------------------
// Kernel 1: e[r] = dot(H_e[r,:], p)
// ---------------------------------------------------------------------------
__global__ void escale_kernel(const float* __restrict__ He,
                              const float* __restrict__ p) {
    int warp = threadIdx.x >> 5;
    int lane = threadIdx.x & 31;
    int row  = blockIdx.x * 8 + warp;
    if (row >= E_EDGES) return;
    const float* hr = He + (size_t)row * IN_E;
    float s = 0.f;
#pragma unroll
    for (int i = 0; i < IN_E; i += 32)
        s += hr[i + lane] * p[i + lane];
#pragma unroll
    for (int off = 16; off > 0; off >>= 1)
        s += __shfl_down_sync(0xffffffffu, s, off);
    if (lane == 0) g_escale[row] = s;
}

// ---------------------------------------------------------------------------
// Kernel 1b: split T and G=T*diag(e) into bf16 hi/lo pairs
// ---------------------------------------------------------------------------
__global__ __launch_bounds__(256)
void convert_kernel(const float* __restrict__ T) {
    unsigned g   = blockIdx.x * 256u + threadIdx.x;
    unsigned row = g >> 11;
    unsigned k4  = (g & 2047u) * 4u;
    size_t base = (size_t)row * E_EDGES + k4;
    float4 t = *(const float4*)(T + base);
    float4 e = *(const float4*)(g_escale + k4);
    float gv[4] = {t.x * e.x, t.y * e.y, t.z * e.z, t.w * e.w};
    float tv[4] = {t.x, t.y, t.z, t.w};
    unsigned short ghi[4], glo[4], thi[4], tlo[4];
#pragma unroll
    for (int i = 0; i < 4; i++) {
        __nv_bfloat16 h, l;
        bsplit(gv[i], h, l);
        ghi[i] = __bfloat16_as_ushort(h); glo[i] = __bfloat16_as_ushort(l);
        bsplit(tv[i], h, l);
        thi[i] = __bfloat16_as_ushort(h); tlo[i] = __bfloat16_as_ushort(l);
    }
#define PACK2(a) make_uint2((unsigned)(a)[0] | ((unsigned)(a)[1] << 16), \
                            (unsigned)(a)[2] | ((unsigned)(a)[3] << 16))
    *(uint2*)(g_Ghi + base) = PACK2(ghi);
    *(uint2*)(g_Glo + base) = PACK2(glo);
    *(uint2*)(g_Thi + base) = PACK2(thi);
    *(uint2*)(g_Tlo + base) = PACK2(tlo);
#undef PACK2
}

// ---------------------------------------------------------------------------
// Kernel 1c: transposed hi/lo splits of H_v and W
// ---------------------------------------------------------------------------
__global__ __launch_bounds__(256)
void convert_hvt_kernel(const float* __restrict__ Hv) {
    __shared__ float tile[32][33];
    int tx = threadIdx.x & 31;
    int ty = threadIdx.x >> 5;
    int n0 = blockIdx.x * 32;
    int k0 = blockIdx.y * 32;
#pragma unroll
    for (int i = ty; i < 32; i += 8)
        tile[i][tx] = Hv[(size_t)(k0 + i) * IN_V + n0 + tx];
    __syncthreads();
#pragma unroll
    for (int i = ty; i < 32; i += 8) {
        float v = tile[tx][i];
        __nv_bfloat16 h, l;
        bsplit(v, h, l);
        size_t idx = (size_t)(n0 + i) * N_NODES + k0 + tx;
        g_HvThi[idx] = h;
        g_HvTlo[idx] = l;
    }
}

__global__ __launch_bounds__(256)
void convert_wt_kernel(const float* __restrict__ W) {
    __shared__ float tile[32][33];
    int tx = threadIdx.x & 31;
    int ty = threadIdx.x >> 5;
    int n0 = blockIdx.x * 32;
    int k0 = blockIdx.y * 32;
#pragma unroll
    for (int i = ty; i < 32; i += 8)
        tile[i][tx] = W[(size_t)(k0 + i) * OUT_V + n0 + tx];
    __syncthreads();
#pragma unroll
    for (int i = ty; i < 32; i += 8) {
        float v = tile[tx][i];
        __nv_bfloat16 h, l;
        bsplit(v, h, l);
        size_t idx = (size_t)(n0 + i) * IN_V + k0 + tx;
        g_WThi[idx] = h;
        g_WTlo[idx] = l;
    }
}

// ---------------------------------------------------------------------------
// Kernel 2: gemm1 = lower-tri 256x128 tiles of M1 = G @ T^T
// 8 warps as 4x2, warp tile 64x64.  Fused Bcomb epilogue + mirror.
// ---------------------------------------------------------------------------
__global__ __launch_bounds__(256, 1)
void gemm1_mma(const float* __restrict__ adj_v) {
    extern __shared__ char smem[];
    uint32_t sb = smem_u32(smem);
    const int tid  = threadIdx.x;
    const int wid  = tid >> 5;
    const int lane = tid & 31;
    const int wr   = wid >> 1;        // 0..3 (64-row bands)
    const int wc   = wid & 1;         // 0..1 (64-col bands)

    // tile id -> (rt, ct): cumulative rt^2+rt, ct <= 2rt+1
    unsigned l = blockIdx.x;
    unsigned rt = (unsigned)((sqrtf(4.f * (float)l + 1.f) - 1.f) * 0.5f);
    while (rt * rt + rt > l) rt--;
    while ((rt + 1u) * (rt + 1u) + (rt + 1u) <= l) rt++;
    unsigned ct = l - (rt * rt + rt);
    const unsigned rowbase = rt * 256u;
    const unsigned colbase = ct * 128u;
    const bool crossing = (ct >= 2u * rt);   // tile touches/crosses diagonal

    float acc[4][8][4];
#pragma unroll
    for (int m = 0; m < 4; m++)
#pragma unroll
        for (int n = 0; n < 8; n++)
#pragma unroll
            for (int i = 0; i < 4; i++) acc[m][n][i] = 0.f;

    auto load_chunk = [&](int c, int s) {
        uint32_t sbase = sb + (uint32_t)s * G1_STAGE;
        unsigned kbase = (unsigned)c * KC;
        // A: 256 rows x 64 bf16 (8 x16B per row), hi+lo : 8 slots each per thread
#pragma unroll
        for (int i = 0; i < 8; i++) {
            int slot = i * 256 + tid;
            int r = slot >> 3, q = slot & 7;
            uint32_t off = swz((uint32_t)(r * 128 + q * 16));
            cpa16(sbase + off,
                  (const void*)(g_Ghi + (size_t)(rowbase + r) * E_EDGES + kbase + q * 8));
            cpa16(sbase + 32768u + off,
                  (const void*)(g_Glo + (size_t)(rowbase + r) * E_EDGES + kbase + q * 8));
        }
        // B: 128 rows x 64 bf16, hi+lo : 4 slots each per thread
#pragma unroll
        for (int i = 0; i < 4; i++) {
            int slot = i * 256 + tid;
            int r = slot >> 3, q = slot & 7;
            uint32_t off = swz((uint32_t)(r * 128 + q * 16));
            cpa16(sbase + 65536u + off,
                  (const void*)(g_Thi + (size_t)(colbase + r) * E_EDGES + kbase + q * 8));
            cpa16(sbase + 81920u + off,
                  (const void*)(g_Tlo + (size_t)(colbase + r) * E_EDGES + kbase + q * 8));
        }
    };

    load_chunk(0, 0); CP_COMMIT();

    const int la_row = lane & 15;
    const int la_kh  = lane >> 4;
    const int gB  = lane >> 3;
    const int rB  = lane & 7;
    const int ntO = gB >> 1;
    const int khB = gB & 1;

    for (int c = 0; c < NCHUNK1; c++) {
        int s = c & 1;
        CP_WAIT0();
        __syncthreads();
        if (c + 1 < NCHUNK1) load_chunk(c + 1, s ^ 1);
        CP_COMMIT();

        uint32_t stage = sb + (uint32_t)s * G1_STAGE;
        uint32_t aHiB = stage;
        uint32_t aLoB = stage + 32768u;
        uint32_t bHiB = stage + 65536u;
        uint32_t bLoB = stage + 81920u;

#pragma unroll
        for (int ks = 0; ks < 4; ks++) {
            uint32_t ahi[4][4], alo[4][4], bhi[8][2], blo[8][2];
#pragma unroll
            for (int mt = 0; mt < 4; mt++) {
                uint32_t off = swz((uint32_t)((wr * 64 + mt * 16 + la_row) * 128
                                              + ks * 32 + la_kh * 16));
                ldsm_x4(ahi[mt][0], ahi[mt][1], ahi[mt][2], ahi[mt][3], aHiB + off);
                ldsm_x4(alo[mt][0], alo[mt][1], alo[mt][2], alo[mt][3], aLoB + off);
            }
#pragma unroll
            for (int p = 0; p < 4; p++) {    // n-tile pairs (2p, 2p+1)
                uint32_t off = swz((uint32_t)((wc * 64 + (p * 2 + ntO) * 8 + rB) * 128
                                              + ks * 32 + khB * 16));
                ldsm_x4(bhi[p * 2][0], bhi[p * 2][1], bhi[p * 2 + 1][0], bhi[p * 2 + 1][1],
                        bHiB + off);
                ldsm_x4(blo[p * 2][0], blo[p * 2][1], blo[p * 2 + 1][0], blo[p * 2 + 1][1],
                        bLoB + off);
            }
#pragma unroll
            for (int mt = 0; mt < 4; mt++)
#pragma unroll
                for (int nt = 0; nt < 8; nt++) {
                    mma_bf16(acc[mt][nt], ahi[mt], bhi[nt]);
                    mma_bf16(acc[mt][nt], ahi[mt], blo[nt]);
                    mma_bf16(acc[mt][nt], alo[mt], bhi[nt]);
                }
        }
    }

    // Epilogue: Bcomb = 0.5*(M1'+1).*adj_v at (r,c), mirror at (c,r).
#pragma unroll
    for (int mt = 0; mt < 4; mt++) {
        unsigned r0 = rowbase + wr * 64 + mt * 16 + (lane >> 2);
        unsigned r1 = r0 + 8;
#pragma unroll
        for (int nt = 0; nt < 8; nt++) {
            unsigned cc = colbase + wc * 64 + nt * 8 + 2 * (lane & 3);
            if (!crossing) {
                // interior: r > c always -> packed direct + mirror, no diag
                float2 a0 = *(const float2*)&adj_v[(size_t)r0 * N_NODES + cc];
                float2 a1 = *(const float2*)&adj_v[(size_t)r1 * N_NODES + cc];
                float b00 = 0.5f * (acc[mt][nt][0] + 1.f) * a0.x;
                float b01 = 0.5f * (acc[mt][nt][1] + 1.f) * a0.y;
                float b10 = 0.5f * (acc[mt][nt][2] + 1.f) * a1.x;
                float b11 = 0.5f * (acc[mt][nt][3] + 1.f) * a1.y;
                __nv_bfloat16 h00, l00, h01, l01, h10, l10, h11, l11;
                bsplit(b00, h00, l00); bsplit(b01, h01, l01);
                bsplit(b10, h10, l10); bsplit(b11, h11, l11);
                *(uint32_t*)&g_Bhi[(size_t)r0 * N_NODES + cc] =
                    (uint32_t)__bfloat16_as_ushort(h00) | ((uint32_t)__bfloat16_as_ushort(h01) << 16);
                *(uint32_t*)&g_Blo[(size_t)r0 * N_NODES + cc] =
                    (uint32_t)__bfloat16_as_ushort(l00) | ((uint32_t)__bfloat16_as_ushort(l01) << 16);
                *(uint32_t*)&g_Bhi[(size_t)r1 * N_NODES + cc] =
                    (uint32_t)__bfloat16_as_ushort(h10) | ((uint32_t)__bfloat16_as_ushort(h11) << 16);
                *(uint32_t*)&g_Blo[(size_t)r1 * N_NODES + cc] =
                    (uint32_t)__bfloat16_as_ushort(l10) | ((uint32_t)__bfloat16_as_ushort(l11) << 16);

                float m00 = 0.5f * (acc[mt][nt][0] + 1.f) * adj_v[(size_t)cc * N_NODES + r0];
                float m01 = 0.5f * (acc[mt][nt][1] + 1.f) * adj_v[(size_t)(cc + 1) * N_NODES + r0];
                float m10 = 0.5f * (acc[mt][nt][2] + 1.f) * adj_v[(size_t)cc * N_NODES + r1];
                float m11 = 0.5f * (acc[mt][nt][3] + 1.f) * adj_v[(size_t)(cc + 1) * N_NODES + r1];
                __nv_bfloat16 h, l2;
                bsplit(m00, h, l2);
                g_Bhi[(size_t)cc * N_NODES + r0] = h;  g_Blo[(size_t)cc * N_NODES + r0] = l2;
                bsplit(m01, h, l2);
                g_Bhi[(size_t)(cc + 1) * N_NODES + r0] = h;  g_Blo[(size_t)(cc + 1) * N_NODES + r0] = l2;
                bsplit(m10, h, l2);
                g_Bhi[(size_t)cc * N_NODES + r1] = h;  g_Blo[(size_t)cc * N_NODES + r1] = l2;
                bsplit(m11, h, l2);
                g_Bhi[(size_t)(cc + 1) * N_NODES + r1] = h;  g_Blo[(size_t)(cc + 1) * N_NODES + r1] = l2;
            } else {
                // crossing tile: per-element predicates (write exactly once)
#pragma unroll
                for (int e = 0; e < 4; e++) {
                    unsigned r = (e < 2) ? r0 : r1;
                    unsigned c2 = cc + (e & 1);
                    float a = acc[mt][nt][e];
                    if (r >= c2) {
                        float av = adj_v[(size_t)r * N_NODES + c2];
                        float bv = (r == c2) ? av : 0.5f * (a + 1.f) * av;
                        __nv_bfloat16 h, l2;
                        bsplit(bv, h, l2);
                        g_Bhi[(size_t)r * N_NODES + c2] = h;
                        g_Blo[(size_t)r * N_NODES + c2] = l2;
                    }
                    if (r > c2) {
                        float bm = 0.5f * (a + 1.f) * adj_v[(size_t)c2 * N_NODES + r];
                        __nv_bfloat16 h, l2;
                        bsplit(bm, h, l2);
                        g_Bhi[(size_t)c2 * N_NODES + r] = h;
                        g_Blo[(size_t)c2 * N_NODES + r] = l2;
                    }
                }
            }
        }
    }
}

// ---------------------------------------------------------------------------
// Shared 128x128 mma mainloop for gemm2/gemm3 (2x4 warps, 64x32 warp tile)
// ---------------------------------------------------------------------------
struct FragCtx { int wr, wc, lane; };

__device__ __forceinline__ void mma_chunk(uint32_t stage, const FragCtx& f,
                                          float acc[4][4][4]) {
    uint32_t aHiB = stage;
    uint32_t aLoB = stage + 16384u;
    uint32_t bHiB = stage + 32768u;
    uint32_t bLoB = stage + 49152u;
    const int lane = f.lane;
    const int la_row = lane & 15;
    const int la_kh  = lane >> 4;
    const int gB   = lane >> 3;
    const int rB   = lane & 7;
    const int ntO  = gB >> 1;
    const int khB  = gB & 1;

#pragma unroll
    for (int ks = 0; ks < 4; ks++) {
        uint32_t ahi[4][4], alo[4][4], bhi[4][2], blo[4][2];
#pragma unroll
        for (int mt = 0; mt < 4; mt++) {
            uint32_t off = swz((uint32_t)((f.wr * 64 + mt * 16 + la_row) * 128
                                          + ks * 32 + la_kh * 16));
            ldsm_x4(ahi[mt][0], ahi[mt][1], ahi[mt][2], ahi[mt][3], aHiB + off);
            ldsm_x4(alo[mt][0], alo[mt][1], alo[mt][2], alo[mt][3], aLoB + off);
        }
#pragma unroll
        for (int p = 0; p < 2; p++) {
            uint32_t off = swz((uint32_t)((f.wc * 32 + (p * 2 + ntO) * 8 + rB) * 128
                                          + ks * 32 + khB * 16));
            ldsm_x4(bhi[p * 2][0], bhi[p * 2][1], bhi[p * 2 + 1][0], bhi[p * 2 + 1][1],
                    bHiB + off);
            ldsm_x4(blo[p * 2][0], blo[p * 2][1], blo[p * 2 + 1][0], blo[p * 2 + 1][1],
                    bLoB + off);
        }
#pragma unroll
        for (int mt = 0; mt < 4; mt++)
#pragma unroll
            for (int nt = 0; nt < 4; nt++) {
                mma_bf16(acc[mt][nt], ahi[mt], bhi[nt]);
                mma_bf16(acc[mt][nt], ahi[mt], blo[nt]);
                mma_bf16(acc[mt][nt], alo[mt], bhi[nt]);
            }
    }
}

// ---------------------------------------------------------------------------
// Kernel 3: Y = Bcomb @ H_v (bf16-split), epilogue emits Y as bf16 hi/lo
// ---------------------------------------------------------------------------
__global__ __launch_bounds__(256, 1)
void gemm2_mma() {
    extern __shared__ char smem[];
    uint32_t sb = smem_u32(smem);
    const int tid  = threadIdx.x;
    const int wid  = tid >> 5;
    const int lane = tid & 31;
    FragCtx f{wid >> 2, wid & 3, lane};

    const unsigned rowbase = blockIdx.y * 128u;
    const unsigned colbase = blockIdx.x * 128u;

    float acc[4][4][4];
#pragma unroll
    for (int m = 0; m < 4; m++)
#pragma unroll
        for (int n = 0; n < 4; n++)
#pragma unroll
            for (int i = 0; i < 4; i++) acc[m][n][i] = 0.f;

    auto load_chunk = [&](int c, int s) {
        uint32_t sbase = sb + (uint32_t)s * STAGE_BYTES;
        unsigned kbase = (unsigned)c * KC;
#pragma unroll
        for (int i = 0; i < 16; i++) {
            const int arr = i >> 2;
            const int ci  = (i & 3) * 256 + tid;
            const int r   = ci >> 3;
            const int q   = ci & 7;
            const __nv_bfloat16* src;
            unsigned grow;
            if (arr == 0)      { src = g_Bhi;   grow = rowbase + r; }
            else if (arr == 1) { src = g_Blo;   grow = rowbase + r; }
            else if (arr == 2) { src = g_HvThi; grow = colbase + r; }
            else               { src = g_HvTlo; grow = colbase + r; }
            cpa16(sbase + (uint32_t)arr * 16384u + swz((uint32_t)(r * 128 + q * 16)),
                  (const void*)(src + (size_t)grow * N_NODES + kbase + q * 8));
        }
    };

    load_chunk(0, 0); CP_COMMIT();
    load_chunk(1, 1); CP_COMMIT();

    for (int c = 0; c < NCHUNK2; c++) {
        CP_WAIT1();
        __syncthreads();
        if (c + 2 < NCHUNK2) load_chunk(c + 2, (c + 2) % NSTAGE);
        CP_COMMIT();
        mma_chunk(sb + (uint32_t)(c % NSTAGE) * STAGE_BYTES, f, acc);
    }

#pragma unroll
    for (int mt = 0; mt < 4; mt++) {
        unsigned r0 = rowbase + f.wr * 64 + mt * 16 + (lane >> 2);
#pragma unroll
        for (int nt = 0; nt < 4; nt++) {
            unsigned cc = colbase + f.wc * 32 + nt * 8 + 2 * (lane & 3);
            __nv_bfloat16 h0, l0, h1, l1;
            bsplit(acc[mt][nt][0], h0, l0); bsplit(acc[mt][nt][1], h1, l1);
            *(uint32_t*)&g_Yhi[(size_t)r0 * IN_V + cc] =
                (uint32_t)__bfloat16_as_ushort(h0) | ((uint32_t)__bfloat16_as_ushort(h1) << 16);
            *(uint32_t*)&g_Ylo[(size_t)r0 * IN_V + cc] =
                (uint32_t)__bfloat16_as_ushort(l0) | ((uint32_t)__bfloat16_as_ushort(l1) << 16);
            bsplit(acc[mt][nt][2], h0, l0); bsplit(acc[mt][nt][3], h1, l1);
            *(uint32_t*)&g_Yhi[(size_t)(r0 + 8) * IN_V + cc] =
                (uint32_t)__bfloat16_as_ushort(h0) | ((uint32_t)__bfloat16_as_ushort(h1) << 16);
            *(uint32_t*)&g_Ylo[(size_t)(r0 + 8) * IN_V + cc] =
                (uint32_t)__bfloat16_as_ushort(l0) | ((uint32_t)__bfloat16_as_ushort(l1) << 16);
        }
    }
}

// ---------------------------------------------------------------------------
// Kernel 4: ret = Y @ W + bias (bf16-split mma), K = IN_V = 512
// ---------------------------------------------------------------------------
__global__ __launch_bounds__(256, 1)
void gemm3_mma(const float* __restrict__ bias, float* __restrict__ out) {
    extern __shared__ char smem[];
    uint32_t sb = smem_u32(smem);
    const int tid  = threadIdx.x;
    const int wid  = tid >> 5;
    const int lane = tid & 31;
    FragCtx f{wid >> 2, wid & 3, lane};

    const unsigned rowbase = blockIdx.y * 128u;
    const unsigned colbase = blockIdx.x * 128u;

    float acc[4][4][4];
#pragma unroll
    for (int m = 0; m < 4; m++)
#pragma unroll
        for (int n = 0; n < 4; n++)
#pragma unroll
            for (int i = 0; i < 4; i++) acc[m][n][i] = 0.f;

    auto load_chunk = [&](int c, int s) {
        uint32_t sbase = sb + (uint32_t)s * STAGE_BYTES;
        unsigned kbase = (unsigned)c * KC;
#pragma unroll
        for (int i = 0; i < 16; i++) {
            const int arr = i >> 2;
            const int ci  = (i & 3) * 256 + tid;
            const int r   = ci >> 3;
            const int q   = ci & 7;
            const __nv_bfloat16* src;
            unsigned grow;
            if (arr == 0)      { src = g_Yhi;  grow = rowbase + r; }
            else if (arr == 1) { src = g_Ylo;  grow = rowbase + r; }
            else if (arr == 2) { src = g_WThi; grow = colbase + r; }
            else               { src = g_WTlo; grow = colbase + r; }
            cpa16(sbase + (uint32_t)arr * 16384u + swz((uint32_t)(r * 128 + q * 16)),
                  (const void*)(src + (size_t)grow * IN_V + kbase + q * 8));
        }
    };

    load_chunk(0, 0); CP_COMMIT();
    load_chunk(1, 1); CP_COMMIT();

    for (int c = 0; c < NCHUNK3; c++) {
        CP_WAIT1();
        __syncthreads();
        if (c + 2 < NCHUNK3) load_chunk(c + 2, (c + 2) % NSTAGE);
        CP_COMMIT();
        mma_chunk(sb + (uint32_t)(c % NSTAGE) * STAGE_BYTES, f, acc);
    }

#pragma unroll
    for (int mt = 0; mt < 4; mt++) {
        unsigned r0 = rowbase + f.wr * 64 + mt * 16 + (lane >> 2);
#pragma unroll
        for (int nt = 0; nt < 4; nt++) {
            unsigned cc = colbase + f.wc * 32 + nt * 8 + 2 * (lane & 3);
            float2 bv = *(const float2*)&bias[cc];
            *(float2*)&out[(size_t)r0 * OUT_V + cc] =
                make_float2(acc[mt][nt][0] + bv.x, acc[mt][nt][1] + bv.y);
            *(float2*)&out[(size_t)(r0 + 8) * OUT_V + cc] =
                make_float2(acc[mt][nt][2] + bv.x, acc[mt][nt][3] + bv.y);
        }
    }
}

// ---------------------------------------------------------------------------
extern "C" void kernel_launch(void* const* d_in, const int* in_sizes, int n_in,
                              void* d_out, int out_size) {
    const float* H_v   = (const float*)d_in[0];
    const float* H_e   = (const float*)d_in[1];
    // d_in[2] = adj_e : unused by the reference
    const float* adj_v = (const float*)d_in[3];
    const float* T     = (const float*)d_in[4];
    const float* W     = (const float*)d_in[5];
    const float* p     = (const float*)d_in[6];
    const float* bias  = (const float*)d_in[7];
    float* out = (float*)d_out;

    static bool attr_done = false;
    if (!attr_done) {
        cudaFuncSetAttribute(gemm1_mma, cudaFuncAttributeMaxDynamicSharedMemorySize, G1_SMEM);
        cudaFuncSetAttribute(gemm2_mma, cudaFuncAttributeMaxDynamicSharedMemorySize, GEMM_SMEM);
        cudaFuncSetAttribute(gemm3_mma, cudaFuncAttributeMaxDynamicSharedMemorySize, GEMM_SMEM);
        attr_done = true;
    }

    // 1. e = H_e @ p^T
    escale_kernel<<<E_EDGES / 8, 256>>>(H_e, p);

    // 1b. bf16 hi/lo split of G = T*diag(e) and T
    convert_kernel<<<(N_NODES * (E_EDGES / 4)) / 256, 256>>>(T);

    // 1c. transposed splits of H_v and W
    convert_hvt_kernel<<<dim3(IN_V / 32, N_NODES / 32), 256>>>(H_v);
    convert_wt_kernel<<<dim3(OUT_V / 32, IN_V / 32), 256>>>(W);

    // 2. lower-tri M1 tiles (256x128) + fused Bcomb bf16 epilogue + mirror
    gemm1_mma<<<NTILE1, 256, G1_SMEM>>>(adj_v);

    // 3. Y = Bcomb @ H_v  -> bf16 hi/lo
    gemm2_mma<<<dim3(IN_V / 128, N_NODES / 128), 256, GEMM_SMEM>>>();

    // 4. ret = Y @ W + bias
    gemm3_mma<<<dim3(OUT_V / 128, N_NODES / 128), 256, GEMM_SMEM>>>(bias, out);

    // 5. second output: H_e passthrough
    int he_elems = in_sizes[1];
    cudaMemcpyAsync(out + ((size_t)out_size - he_elems), H_e,
                    (size_t)he_elems * sizeof(float),
                    cudaMemcpyDeviceToDevice, 0);
}

// round 9
// speedup vs baseline: 1.3745x; 1.3745x over previous
#include <cuda_runtime.h>
#include <cuda_fp16.h>
#include <cstdint>
#include <cstddef>

// ---------------------------------------------------------------------------
// GraphConvolution (base sm_103, mma.sync HMMA path):
//   e     = H_e @ p^T
//   M1    = (T*diag(e)) @ T^T        symmetric -> lower-tri 256x128 tiles
//   Bcomb = 0.5*(M1'+1) .* adj_v     fused into gemm1 epilogue, fp16 hi/lo
//   Y     = Bcomb @ H_v              fp16 2-product mma -> Y hi/lo
//   ret   = Y @ W + bias             fp16 2-product mma
//   out   = concat(ret, H_e)
// Numeric scheme: asymmetric Ozaki split -- A-side split into fp16 hi+lo
// (exact to ~2^-22), B-side single fp16 (error 2^-12). Two MMA products per
// GEMM instead of three; fp32 accumulate.
// ---------------------------------------------------------------------------

#define N_NODES 4096
#define E_EDGES 8192
#define IN_V    512
#define OUT_V   512
#define IN_E    128
#define KC      64
#define NCHUNK1 (E_EDGES / KC)    // 128
#define NCHUNK2 (N_NODES / KC)    // 64
#define NCHUNK3 (IN_V / KC)       // 8

// gemm1: 256x128 tiles over lower triangle: ct <= 2*rt+1, rt in [0,16)
#define NTILE1  272               // sum_{rt<16} (2rt+2)

// gemm1 stage: Ahi(32K)+Alo(32K)+Bf(16K) = 80KB, 2 stages
#define G1_STAGE  81920
#define G1_SMEM   (2 * G1_STAGE)
// gemm2/3 stage: Ahi(16K)+Alo(16K)+Bf(16K) = 48KB, 3 stages
#define G2_STAGE  49152
#define G2_NSTAGE 3
#define G2_SMEM   (G2_NSTAGE * G2_STAGE)

// Static device scratch
__device__ float g_escale[E_EDGES];
__device__ __half g_Ghi[(size_t)N_NODES * E_EDGES];   // 64 MB each
__device__ __half g_Glo[(size_t)N_NODES * E_EDGES];
__device__ __half g_Tf [(size_t)N_NODES * E_EDGES];
__device__ __half g_Bhi[(size_t)N_NODES * N_NODES];   // 32 MB each
__device__ __half g_Blo[(size_t)N_NODES * N_NODES];
__device__ __half g_HvT[(size_t)IN_V * N_NODES];      // 4 MB
__device__ __half g_Yhi[(size_t)N_NODES * IN_V];      // 4 MB each
__device__ __half g_Ylo[(size_t)N_NODES * IN_V];
__device__ __half g_WT [(size_t)OUT_V * IN_V];        // 0.5 MB

// ------------------------------ helpers ------------------------------------
__device__ __forceinline__ uint32_t smem_u32(const void* p) {
    uint32_t a;
    asm("{ .reg .u64 t; cvta.to.shared.u64 t, %1; cvt.u32.u64 %0, t; }"
        : "=r"(a) : "l"(p));
    return a;
}
__device__ __forceinline__ uint32_t swz(uint32_t x) { return x ^ ((x >> 3) & 0x70u); }

__device__ __forceinline__ void ldsm_x4(uint32_t& a0, uint32_t& a1,
                                        uint32_t& a2, uint32_t& a3, uint32_t addr) {
    asm volatile("ldmatrix.sync.aligned.m8n8.x4.shared.b16 {%0,%1,%2,%3}, [%4];"
                 : "=r"(a0), "=r"(a1), "=r"(a2), "=r"(a3) : "r"(addr));
}
__device__ __forceinline__ void mma_f16(float* d, const uint32_t* a, const uint32_t* b) {
    asm volatile(
        "mma.sync.aligned.m16n8k16.row.col.f32.f16.f16.f32 "
        "{%0,%1,%2,%3}, {%4,%5,%6,%7}, {%8,%9}, {%0,%1,%2,%3};"
        : "+f"(d[0]), "+f"(d[1]), "+f"(d[2]), "+f"(d[3])
        : "r"(a[0]), "r"(a[1]), "r"(a[2]), "r"(a[3]), "r"(b[0]), "r"(b[1]));
}
__device__ __forceinline__ void hsplit(float v, __half& h, __half& l) {
    h = __float2half(v);
    l = __float2half(v - __half2float(h));
}
__device__ __forceinline__ void cpa16(uint32_t dst, const void* src) {
    asm volatile("cp.async.cg.shared.global [%0], [%1], 16;" :: "r"(dst), "l"(src));
}
#define CP_COMMIT() asm volatile("cp.async.commit_group;" ::: "memory")
#define CP_WAIT0()  asm volatile("cp.async.wait_group 0;" ::: "memory")
#define CP_WAIT1()  asm volatile("cp.async.wait_group 1;" ::: "memory")

// ---------------------------------------------------------------------------
// Kernel 1: e[r] = dot(H_e[r,:], p)
// ---------------------------------------------------------------------------
__global__ void escale_kernel(const float* __restrict__ He,
                              const float* __restrict__ p) {
    int warp = threadIdx.x >> 5;
    int lane = threadIdx.x & 31;
    int row  = blockIdx.x * 8 + warp;
    if (row >= E_EDGES) return;
    const float* hr = He + (size_t)row * IN_E;
    float s = 0.f;
#pragma unroll
    for (int i = 0; i < IN_E; i += 32)
        s += hr[i + lane] * p[i + lane];
#pragma unroll
    for (int off = 16; off > 0; off >>= 1)
        s += __shfl_down_sync(0xffffffffu, s, off);
    if (lane == 0) g_escale[row] = s;
}

// ---------------------------------------------------------------------------
// Kernel 1b: G = T*diag(e) -> fp16 hi/lo;  T -> single fp16
// ---------------------------------------------------------------------------
__global__ __launch_bounds__(256)
void convert_kernel(const float* __restrict__ T) {
    unsigned g   = blockIdx.x * 256u + threadIdx.x;
    unsigned row = g >> 11;
    unsigned k4  = (g & 2047u) * 4u;
    size_t base = (size_t)row * E_EDGES + k4;
    float4 t = *(const float4*)(T + base);
    float4 e = *(const float4*)(g_escale + k4);
    float gv[4] = {t.x * e.x, t.y * e.y, t.z * e.z, t.w * e.w};
    float tv[4] = {t.x, t.y, t.z, t.w};
    unsigned short ghi[4], glo[4], tf[4];
#pragma unroll
    for (int i = 0; i < 4; i++) {
        __half h, l;
        hsplit(gv[i], h, l);
        ghi[i] = __half_as_ushort(h);
        glo[i] = __half_as_ushort(l);
        tf[i]  = __half_as_ushort(__float2half(tv[i]));
    }
#define PACK2(a) make_uint2((unsigned)(a)[0] | ((unsigned)(a)[1] << 16), \
                            (unsigned)(a)[2] | ((unsigned)(a)[3] << 16))
    *(uint2*)(g_Ghi + base) = PACK2(ghi);
    *(uint2*)(g_Glo + base) = PACK2(glo);
    *(uint2*)(g_Tf  + base) = PACK2(tf);
#undef PACK2
}

// ---------------------------------------------------------------------------
// Kernel 1c: transposed fp16 of H_v (-> [IN_V][N]) and W (-> [OUT_V][IN_V])
// ---------------------------------------------------------------------------
__global__ __launch_bounds__(256)
void convert_hvt_kernel(const float* __restrict__ Hv) {
    __shared__ float tile[32][33];
    int tx = threadIdx.x & 31;
    int ty = threadIdx.x >> 5;
    int n0 = blockIdx.x * 32;
    int k0 = blockIdx.y * 32;
#pragma unroll
    for (int i = ty; i < 32; i += 8)
        tile[i][tx] = Hv[(size_t)(k0 + i) * IN_V + n0 + tx];
    __syncthreads();
#pragma unroll
    for (int i = ty; i < 32; i += 8)
        g_HvT[(size_t)(n0 + i) * N_NODES + k0 + tx] = __float2half(tile[tx][i]);
}

__global__ __launch_bounds__(256)
void convert_wt_kernel(const float* __restrict__ W) {
    __shared__ float tile[32][33];
    int tx = threadIdx.x & 31;
    int ty = threadIdx.x >> 5;
    int n0 = blockIdx.x * 32;
    int k0 = blockIdx.y * 32;
#pragma unroll
    for (int i = ty; i < 32; i += 8)
        tile[i][tx] = W[(size_t)(k0 + i) * OUT_V + n0 + tx];
    __syncthreads();
#pragma unroll
    for (int i = ty; i < 32; i += 8)
        g_WT[(size_t)(n0 + i) * IN_V + k0 + tx] = __float2half(tile[tx][i]);
}

// ---------------------------------------------------------------------------
// Kernel 2: gemm1 = lower-tri 256x128 tiles of M1 = G @ T^T  (2-product fp16)
// 8 warps as 4x2, warp tile 64x64.  Fused Bcomb epilogue + mirror.
// ---------------------------------------------------------------------------
__global__ __launch_bounds__(256, 1)
void gemm1_mma(const float* __restrict__ adj_v) {
    extern __shared__ char smem[];
    uint32_t sb = smem_u32(smem);
    const int tid  = threadIdx.x;
    const int wid  = tid >> 5;
    const int lane = tid & 31;
    const int wr   = wid >> 1;        // 0..3 (64-row bands)
    const int wc   = wid & 1;         // 0..1 (64-col bands)

    unsigned l = blockIdx.x;
    unsigned rt = (unsigned)((sqrtf(4.f * (float)l + 1.f) - 1.f) * 0.5f);
    while (rt * rt + rt > l) rt--;
    while ((rt + 1u) * (rt + 1u) + (rt + 1u) <= l) rt++;
    unsigned ct = l - (rt * rt + rt);
    const unsigned rowbase = rt * 256u;
    const unsigned colbase = ct * 128u;
    const bool crossing = (ct >= 2u * rt);

    float acc[4][8][4];
#pragma unroll
    for (int m = 0; m < 4; m++)
#pragma unroll
        for (int n = 0; n < 8; n++)
#pragma unroll
            for (int i = 0; i < 4; i++) acc[m][n][i] = 0.f;

    auto load_chunk = [&](int c, int s) {
        uint32_t sbase = sb + (uint32_t)s * G1_STAGE;
        unsigned kbase = (unsigned)c * KC;
#pragma unroll
        for (int i = 0; i < 8; i++) {            // A hi + lo: 256 rows
            int slot = i * 256 + tid;
            int r = slot >> 3, q = slot & 7;
            uint32_t off = swz((uint32_t)(r * 128 + q * 16));
            cpa16(sbase + off,
                  (const void*)(g_Ghi + (size_t)(rowbase + r) * E_EDGES + kbase + q * 8));
            cpa16(sbase + 32768u + off,
                  (const void*)(g_Glo + (size_t)(rowbase + r) * E_EDGES + kbase + q * 8));
        }
#pragma unroll
        for (int i = 0; i < 4; i++) {            // B: 128 rows
            int slot = i * 256 + tid;
            int r = slot >> 3, q = slot & 7;
            uint32_t off = swz((uint32_t)(r * 128 + q * 16));
            cpa16(sbase + 65536u + off,
                  (const void*)(g_Tf + (size_t)(colbase + r) * E_EDGES + kbase + q * 8));
        }
    };

    load_chunk(0, 0); CP_COMMIT();

    const int la_row = lane & 15;
    const int la_kh  = lane >> 4;
    const int gB  = lane >> 3;
    const int rB  = lane & 7;
    const int ntO = gB >> 1;
    const int khB = gB & 1;

    for (int c = 0; c < NCHUNK1; c++) {
        int s = c & 1;
        CP_WAIT0();
        __syncthreads();
        if (c + 1 < NCHUNK1) load_chunk(c + 1, s ^ 1);
        CP_COMMIT();

        uint32_t stage = sb + (uint32_t)s * G1_STAGE;
        uint32_t aHiB = stage;
        uint32_t aLoB = stage + 32768u;
        uint32_t bB   = stage + 65536u;

#pragma unroll
        for (int ks = 0; ks < 4; ks++) {
            uint32_t ahi[4][4], alo[4][4], bf[8][2];
#pragma unroll
            for (int mt = 0; mt < 4; mt++) {
                uint32_t off = swz((uint32_t)((wr * 64 + mt * 16 + la_row) * 128
                                              + ks * 32 + la_kh * 16));
                ldsm_x4(ahi[mt][0], ahi[mt][1], ahi[mt][2], ahi[mt][3], aHiB + off);
                ldsm_x4(alo[mt][0], alo[mt][1], alo[mt][2], alo[mt][3], aLoB + off);
            }
#pragma unroll
            for (int p = 0; p < 4; p++) {
                uint32_t off = swz((uint32_t)((wc * 64 + (p * 2 + ntO) * 8 + rB) * 128
                                              + ks * 32 + khB * 16));
                ldsm_x4(bf[p * 2][0], bf[p * 2][1], bf[p * 2 + 1][0], bf[p * 2 + 1][1],
                        bB + off);
            }
#pragma unroll
            for (int mt = 0; mt < 4; mt++)
#pragma unroll
                for (int nt = 0; nt < 8; nt++) {
                    mma_f16(acc[mt][nt], ahi[mt], bf[nt]);
                    mma_f16(acc[mt][nt], alo[mt], bf[nt]);
                }
        }
    }

    // Epilogue: Bcomb = 0.5*(M1'+1).*adj_v at (r,c), mirror at (c,r).
#pragma unroll
    for (int mt = 0; mt < 4; mt++) {
        unsigned r0 = rowbase + wr * 64 + mt * 16 + (lane >> 2);
        unsigned r1 = r0 + 8;
#pragma unroll
        for (int nt = 0; nt < 8; nt++) {
            unsigned cc = colbase + wc * 64 + nt * 8 + 2 * (lane & 3);
            if (!crossing) {
                float2 a0 = *(const float2*)&adj_v[(size_t)r0 * N_NODES + cc];
                float2 a1 = *(const float2*)&adj_v[(size_t)r1 * N_NODES + cc];
                float b00 = 0.5f * (acc[mt][nt][0] + 1.f) * a0.x;
                float b01 = 0.5f * (acc[mt][nt][1] + 1.f) * a0.y;
                float b10 = 0.5f * (acc[mt][nt][2] + 1.f) * a1.x;
                float b11 = 0.5f * (acc[mt][nt][3] + 1.f) * a1.y;
                __half h00, l00, h01, l01, h10, l10, h11, l11;
                hsplit(b00, h00, l00); hsplit(b01, h01, l01);
                hsplit(b10, h10, l10); hsplit(b11, h11, l11);
                *(uint32_t*)&g_Bhi[(size_t)r0 * N_NODES + cc] =
                    (uint32_t)__half_as_ushort(h00) | ((uint32_t)__half_as_ushort(h01) << 16);
                *(uint32_t*)&g_Blo[(size_t)r0 * N_NODES + cc] =
                    (uint32_t)__half_as_ushort(l00) | ((uint32_t)__half_as_ushort(l01) << 16);
                *(uint32_t*)&g_Bhi[(size_t)r1 * N_NODES + cc] =
                    (uint32_t)__half_as_ushort(h10) | ((uint32_t)__half_as_ushort(h11) << 16);
                *(uint32_t*)&g_Blo[(size_t)r1 * N_NODES + cc] =
                    (uint32_t)__half_as_ushort(l10) | ((uint32_t)__half_as_ushort(l11) << 16);

                float m00 = 0.5f * (acc[mt][nt][0] + 1.f) * adj_v[(size_t)cc * N_NODES + r0];
                float m01 = 0.5f * (acc[mt][nt][1] + 1.f) * adj_v[(size_t)(cc + 1) * N_NODES + r0];
                float m10 = 0.5f * (acc[mt][nt][2] + 1.f) * adj_v[(size_t)cc * N_NODES + r1];
                float m11 = 0.5f * (acc[mt][nt][3] + 1.f) * adj_v[(size_t)(cc + 1) * N_NODES + r1];
                __half h, l2;
                hsplit(m00, h, l2);
                g_Bhi[(size_t)cc * N_NODES + r0] = h;  g_Blo[(size_t)cc * N_NODES + r0] = l2;
                hsplit(m01, h, l2);
                g_Bhi[(size_t)(cc + 1) * N_NODES + r0] = h;  g_Blo[(size_t)(cc + 1) * N_NODES + r0] = l2;
                hsplit(m10, h, l2);
                g_Bhi[(size_t)cc * N_NODES + r1] = h;  g_Blo[(size_t)cc * N_NODES + r1] = l2;
                hsplit(m11, h, l2);
                g_Bhi[(size_t)(cc + 1) * N_NODES + r1] = h;  g_Blo[(size_t)(cc + 1) * N_NODES + r1] = l2;
            } else {
#pragma unroll
                for (int e = 0; e < 4; e++) {
                    unsigned r = (e < 2) ? r0 : r1;
                    unsigned c2 = cc + (e & 1);
                    float a = acc[mt][nt][e];
                    if (r >= c2) {
                        float av = adj_v[(size_t)r * N_NODES + c2];
                        float bv = (r == c2) ? av : 0.5f * (a + 1.f) * av;
                        __half h, l2;
                        hsplit(bv, h, l2);
                        g_Bhi[(size_t)r * N_NODES + c2] = h;
                        g_Blo[(size_t)r * N_NODES + c2] = l2;
                    }
                    if (r > c2) {
                        float bm = 0.5f * (a + 1.f) * adj_v[(size_t)c2 * N_NODES + r];
                        __half h, l2;
                        hsplit(bm, h, l2);
                        g_Bhi[(size_t)c2 * N_NODES + r] = h;
                        g_Blo[(size_t)c2 * N_NODES + r] = l2;
                    }
                }
            }
        }
    }
}

// ---------------------------------------------------------------------------
// Shared 128x128 2-product mainloop for gemm2/gemm3 (2x4 warps, 64x32 tile)
// ---------------------------------------------------------------------------
struct FragCtx { int wr, wc, lane; };

__device__ __forceinline__ void mma_chunk2(uint32_t stage, const FragCtx& f,
                                           float acc[4][4][4]) {
    uint32_t aHiB = stage;
    uint32_t aLoB = stage + 16384u;
    uint32_t bB   = stage + 32768u;
    const int lane = f.lane;
    const int la_row = lane & 15;
    const int la_kh  = lane >> 4;
    const int gB   = lane >> 3;
    const int rB   = lane & 7;
    const int ntO  = gB >> 1;
    const int khB  = gB & 1;

#pragma unroll
    for (int ks = 0; ks < 4; ks++) {
        uint32_t ahi[4][4], alo[4][4], bf[4][2];
#pragma unroll
        for (int mt = 0; mt < 4; mt++) {
            uint32_t off = swz((uint32_t)((f.wr * 64 + mt * 16 + la_row) * 128
                                          + ks * 32 + la_kh * 16));
            ldsm_x4(ahi[mt][0], ahi[mt][1], ahi[mt][2], ahi[mt][3], aHiB + off);
            ldsm_x4(alo[mt][0], alo[mt][1], alo[mt][2], alo[mt][3], aLoB + off);
        }
#pragma unroll
        for (int p = 0; p < 2; p++) {
            uint32_t off = swz((uint32_t)((f.wc * 32 + (p * 2 + ntO) * 8 + rB) * 128
                                          + ks * 32 + khB * 16));
            ldsm_x4(bf[p * 2][0], bf[p * 2][1], bf[p * 2 + 1][0], bf[p * 2 + 1][1],
                    bB + off);
        }
#pragma unroll
        for (int mt = 0; mt < 4; mt++)
#pragma unroll
            for (int nt = 0; nt < 4; nt++) {
                mma_f16(acc[mt][nt], ahi[mt], bf[nt]);
                mma_f16(acc[mt][nt], alo[mt], bf[nt]);
            }
    }
}

// ---------------------------------------------------------------------------
// Kernel 3: Y = Bcomb @ H_v (2-product), epilogue emits Y as fp16 hi/lo
// ---------------------------------------------------------------------------
__global__ __launch_bounds__(256, 1)
void gemm2_mma() {
    extern __shared__ char smem[];
    uint32_t sb = smem_u32(smem);
    const int tid  = threadIdx.x;
    const int wid  = tid >> 5;
    const int lane = tid & 31;
    FragCtx f{wid >> 2, wid & 3, lane};

    const unsigned rowbase = blockIdx.y * 128u;
    const unsigned colbase = blockIdx.x * 128u;

    float acc[4][4][4];
#pragma unroll
    for (int m = 0; m < 4; m++)
#pragma unroll
        for (int n = 0; n < 4; n++)
#pragma unroll
            for (int i = 0; i < 4; i++) acc[m][n][i] = 0.f;

    auto load_chunk = [&](int c, int s) {
        uint32_t sbase = sb + (uint32_t)s * G2_STAGE;
        unsigned kbase = (unsigned)c * KC;
#pragma unroll
        for (int i = 0; i < 12; i++) {
            const int arr = i >> 2;                 // 0:Ahi 1:Alo 2:B
            const int ci  = (i & 3) * 256 + tid;
            const int r   = ci >> 3;
            const int q   = ci & 7;
            const __half* src;
            unsigned grow;
            if (arr == 0)      { src = g_Bhi; grow = rowbase + r; }
            else if (arr == 1) { src = g_Blo; grow = rowbase + r; }
            else               { src = g_HvT; grow = colbase + r; }
            cpa16(sbase + (uint32_t)arr * 16384u + swz((uint32_t)(r * 128 + q * 16)),
                  (const void*)(src + (size_t)grow * N_NODES + kbase + q * 8));
        }
    };

    load_chunk(0, 0); CP_COMMIT();
    load_chunk(1, 1); CP_COMMIT();

    for (int c = 0; c < NCHUNK2; c++) {
        CP_WAIT1();
        __syncthreads();
        if (c + 2 < NCHUNK2) load_chunk(c + 2, (c + 2) % G2_NSTAGE);
        CP_COMMIT();
        mma_chunk2(sb + (uint32_t)(c % G2_NSTAGE) * G2_STAGE, f, acc);
    }

#pragma unroll
    for (int mt = 0; mt < 4; mt++) {
        unsigned r0 = rowbase + f.wr * 64 + mt * 16 + (lane >> 2);
#pragma unroll
        for (int nt = 0; nt < 4; nt++) {
            unsigned cc = colbase + f.wc * 32 + nt * 8 + 2 * (lane & 3);
            __half h0, l0, h1, l1;
            hsplit(acc[mt][nt][0], h0, l0); hsplit(acc[mt][nt][1], h1, l1);
            *(uint32_t*)&g_Yhi[(size_t)r0 * IN_V + cc] =
                (uint32_t)__half_as_ushort(h0) | ((uint32_t)__half_as_ushort(h1) << 16);
            *(uint32_t*)&g_Ylo[(size_t)r0 * IN_V + cc] =
                (uint32_t)__half_as_ushort(l0) | ((uint32_t)__half_as_ushort(l1) << 16);
            hsplit(acc[mt][nt][2], h0, l0); hsplit(acc[mt][nt][3], h1, l1);
            *(uint32_t*)&g_Yhi[(size_t)(r0 + 8) * IN_V + cc] =
                (uint32_t)__half_as_ushort(h0) | ((uint32_t)__half_as_ushort(h1) << 16);
            *(uint32_t*)&g_Ylo[(size_t)(r0 + 8) * IN_V + cc] =
                (uint32_t)__half_as_ushort(l0) | ((uint32_t)__half_as_ushort(l1) << 16);
        }
    }
}

// ---------------------------------------------------------------------------
// Kernel 4: ret = Y @ W + bias (2-product), K = IN_V = 512
// ---------------------------------------------------------------------------
__global__ __launch_bounds__(256, 1)
void gemm3_mma(const float* __restrict__ bias, float* __restrict__ out) {
    extern __shared__ char smem[];
    uint32_t sb = smem_u32(smem);
    const int tid  = threadIdx.x;
    const int wid  = tid >> 5;
    const int lane = tid & 31;
    FragCtx f{wid >> 2, wid & 3, lane};

    const unsigned rowbase = blockIdx.y * 128u;
    const unsigned colbase = blockIdx.x * 128u;

    float acc[4][4][4];
#pragma unroll
    for (int m = 0; m < 4; m++)
#pragma unroll
        for (int n = 0; n < 4; n++)
#pragma unroll
            for (int i = 0; i < 4; i++) acc[m][n][i] = 0.f;

    auto load_chunk = [&](int c, int s) {
        uint32_t sbase = sb + (uint32_t)s * G2_STAGE;
        unsigned kbase = (unsigned)c * KC;
#pragma unroll
        for (int i = 0; i < 12; i++) {
            const int arr = i >> 2;
            const int ci  = (i & 3) * 256 + tid;
            const int r   = ci >> 3;
            const int q   = ci & 7;
            const __half* src;
            unsigned grow;
            if (arr == 0)      { src = g_Yhi; grow = rowbase + r; }
            else if (arr == 1) { src = g_Ylo; grow = rowbase + r; }
            else               { src = g_WT;  grow = colbase + r; }
            cpa16(sbase + (uint32_t)arr * 16384u + swz((uint32_t)(r * 128 + q * 16)),
                  (const void*)(src + (size_t)grow * IN_V + kbase + q * 8));
        }
    };

    load_chunk(0, 0); CP_COMMIT();
    load_chunk(1, 1); CP_COMMIT();

    for (int c = 0; c < NCHUNK3; c++) {
        CP_WAIT1();
        __syncthreads();
        if (c + 2 < NCHUNK3) load_chunk(c + 2, (c + 2) % G2_NSTAGE);
        CP_COMMIT();
        mma_chunk2(sb + (uint32_t)(c % G2_NSTAGE) * G2_STAGE, f, acc);
    }

#pragma unroll
    for (int mt = 0; mt < 4; mt++) {
        unsigned r0 = rowbase + f.wr * 64 + mt * 16 + (lane >> 2);
#pragma unroll
        for (int nt = 0; nt < 4; nt++) {
            unsigned cc = colbase + f.wc * 32 + nt * 8 + 2 * (lane & 3);
            float2 bv = *(const float2*)&bias[cc];
            *(float2*)&out[(size_t)r0 * OUT_V + cc] =
                make_float2(acc[mt][nt][0] + bv.x, acc[mt][nt][1] + bv.y);
            *(float2*)&out[(size_t)(r0 + 8) * OUT_V + cc] =
                make_float2(acc[mt][nt][2] + bv.x, acc[mt][nt][3] + bv.y);
        }
    }
}

// ---------------------------------------------------------------------------
extern "C" void kernel_launch(void* const* d_in, const int* in_sizes, int n_in,
                              void* d_out, int out_size) {
    const float* H_v   = (const float*)d_in[0];
    const float* H_e   = (const float*)d_in[1];
    // d_in[2] = adj_e : unused by the reference
    const float* adj_v = (const float*)d_in[3];
    const float* T     = (const float*)d_in[4];
    const float* W     = (const float*)d_in[5];
    const float* p     = (const float*)d_in[6];
    const float* bias  = (const float*)d_in[7];
    float* out = (float*)d_out;

    static bool attr_done = false;
    if (!attr_done) {
        cudaFuncSetAttribute(gemm1_mma, cudaFuncAttributeMaxDynamicSharedMemorySize, G1_SMEM);
        cudaFuncSetAttribute(gemm2_mma, cudaFuncAttributeMaxDynamicSharedMemorySize, G2_SMEM);
        cudaFuncSetAttribute(gemm3_mma, cudaFuncAttributeMaxDynamicSharedMemorySize, G2_SMEM);
        attr_done = true;
    }

    // 1. e = H_e @ p^T
    escale_kernel<<<E_EDGES / 8, 256>>>(H_e, p);

    // 1b. fp16 split of G = T*diag(e); T -> fp16
    convert_kernel<<<(N_NODES * (E_EDGES / 4)) / 256, 256>>>(T);

    // 1c. transposed fp16 of H_v and W
    convert_hvt_kernel<<<dim3(IN_V / 32, N_NODES / 32), 256>>>(H_v);
    convert_wt_kernel<<<dim3(OUT_V / 32, IN_V / 32), 256>>>(W);

    // 2. lower-tri M1 tiles (256x128) + fused Bcomb fp16 epilogue + mirror
    gemm1_mma<<<NTILE1, 256, G1_SMEM>>>(adj_v);

    // 3. Y = Bcomb @ H_v  -> fp16 hi/lo
    gemm2_mma<<<dim3(IN_V / 128, N_NODES / 128), 256, G2_SMEM>>>();

    // 4. ret = Y @ W + bias
    gemm3_mma<<<dim3(OUT_V / 128, N_NODES / 128), 256, G2_SMEM>>>(bias, out);

    // 5. second output: H_e passthrough
    int he_elems = in_sizes[1];
    cudaMemcpyAsync(out + ((size_t)out_size - he_elems), H_e,
                    (size_t)he_elems * sizeof(float),
                    cudaMemcpyDeviceToDevice, 0);
}

// round 10
// speedup vs baseline: 2.4405x; 1.7756x over previous
#include <cuda_runtime.h>
#include <cuda_fp16.h>
#include <cstdint>
#include <cstddef>

// ---------------------------------------------------------------------------
// GraphConvolution (base sm_103, mma.sync HMMA):
//   e     = H_e @ p^T
//   M1    = (T*diag(e)) @ T^T        lower-tri 256x128 tiles, single-fp16 MMA
//   Bcomb = 0.5*(M1'+1) .* adj_v     fused epilogue -> single fp16, smem-staged
//   HvWT  = (W^T split) @ H_v^T      fp16 2-product (W exact), [OUT_V][N]
//   ret   = Bcomb @ HvWT^T + bias    single-product fp16 mma -> out
//   out   = concat(ret, H_e)
// Error budget: 5 single-fp16 operands x 2.24e-4 (calibrated R6/R9)
// -> ~5.0e-4 rel_err, 2x margin under 1e-3.
// ---------------------------------------------------------------------------

#define N_NODES 4096
#define E_EDGES 8192
#define IN_V    512
#define OUT_V   512
#define IN_E    128
#define KC      64
#define NCHUNK1 (E_EDGES / KC)    // 128
#define NCHUNKF (N_NODES / KC)    // 64
#define NCHUNKH (IN_V / KC)       // 8
#define NTILE1  272               // lower-tri 256x128 tiles

// gemm1: stage = A(Gf 256x64=32K) + B(Tf 128x64=16K) = 48K, 3 stages
#define G1_STAGE  49152
#define G1_SMEM   (3 * G1_STAGE)      // 147456 (epilogue needs 102400)
// hvw: 2-product stage = 48K x 3
#define H_STAGE   49152
#define H_SMEM    (3 * H_STAGE)
// final: single-product stage = 32K x 4
#define F_STAGE   32768
#define F_SMEM    (4 * F_STAGE)

// Static device scratch
__device__ float g_escale[E_EDGES];
__device__ __half g_Gf [(size_t)N_NODES * E_EDGES];   // 64 MB
__device__ __half g_Tf [(size_t)N_NODES * E_EDGES];   // 64 MB
__device__ __half g_Bf [(size_t)N_NODES * N_NODES];   // 32 MB
__device__ __half g_Hvf[(size_t)N_NODES * IN_V];      // 4 MB
__device__ __half g_WThi[(size_t)OUT_V * IN_V];
__device__ __half g_WTlo[(size_t)OUT_V * IN_V];
__device__ __half g_HvWT[(size_t)OUT_V * N_NODES];    // 4 MB, [n][j]

// ------------------------------ helpers ------------------------------------
__device__ __forceinline__ uint32_t smem_u32(const void* p) {
    uint32_t a;
    asm("{ .reg .u64 t; cvta.to.shared.u64 t, %1; cvt.u32.u64 %0, t; }"
        : "=r"(a) : "l"(p));
    return a;
}
__device__ __forceinline__ uint32_t swz(uint32_t x) { return x ^ ((x >> 3) & 0x70u); }

__device__ __forceinline__ void ldsm_x4(uint32_t& a0, uint32_t& a1,
                                        uint32_t& a2, uint32_t& a3, uint32_t addr) {
    asm volatile("ldmatrix.sync.aligned.m8n8.x4.shared.b16 {%0,%1,%2,%3}, [%4];"
                 : "=r"(a0), "=r"(a1), "=r"(a2), "=r"(a3) : "r"(addr));
}
__device__ __forceinline__ void mma_f16(float* d, const uint32_t* a, const uint32_t* b) {
    asm volatile(
        "mma.sync.aligned.m16n8k16.row.col.f32.f16.f16.f32 "
        "{%0,%1,%2,%3}, {%4,%5,%6,%7}, {%8,%9}, {%0,%1,%2,%3};"
        : "+f"(d[0]), "+f"(d[1]), "+f"(d[2]), "+f"(d[3])
        : "r"(a[0]), "r"(a[1]), "r"(a[2]), "r"(a[3]), "r"(b[0]), "r"(b[1]));
}
__device__ __forceinline__ void hsplit(float v, __half& h, __half& l) {
    h = __float2half(v);
    l = __float2half(v - __half2float(h));
}
__device__ __forceinline__ uint32_t hpack(__half a, __half b) {
    return (uint32_t)__half_as_ushort(a) | ((uint32_t)__half_as_ushort(b) << 16);
}
__device__ __forceinline__ void cpa16(uint32_t dst, const void* src) {
    asm volatile("cp.async.cg.shared.global [%0], [%1], 16;" :: "r"(dst), "l"(src));
}
#define CP_COMMIT() asm volatile("cp.async.commit_group;" ::: "memory")
#define CP_WAIT1()  asm volatile("cp.async.wait_group 1;" ::: "memory")
#define CP_WAIT2()  asm volatile("cp.async.wait_group 2;" ::: "memory")

// ---------------------------------------------------------------------------
// Kernel 1: e[r] = dot(H_e[r,:], p)
// ---------------------------------------------------------------------------
__global__ void escale_kernel(const float* __restrict__ He,
                              const float* __restrict__ p) {
    int warp = threadIdx.x >> 5;
    int lane = threadIdx.x & 31;
    int row  = blockIdx.x * 8 + warp;
    if (row >= E_EDGES) return;
    const float* hr = He + (size_t)row * IN_E;
    float s = 0.f;
#pragma unroll
    for (int i = 0; i < IN_E; i += 32)
        s += hr[i + lane] * p[i + lane];
#pragma unroll
    for (int off = 16; off > 0; off >>= 1)
        s += __shfl_down_sync(0xffffffffu, s, off);
    if (lane == 0) g_escale[row] = s;
}

// ---------------------------------------------------------------------------
// Kernel 1b: Gf = fp16(T*diag(e)); Tf = fp16(T)
// ---------------------------------------------------------------------------
__global__ __launch_bounds__(256)
void convert_kernel(const float* __restrict__ T) {
    unsigned g   = blockIdx.x * 256u + threadIdx.x;
    unsigned row = g >> 11;
    unsigned k4  = (g & 2047u) * 4u;
    size_t base = (size_t)row * E_EDGES + k4;
    float4 t = *(const float4*)(T + base);
    float4 e = *(const float4*)(g_escale + k4);
    uint2 gf = make_uint2(hpack(__float2half(t.x * e.x), __float2half(t.y * e.y)),
                          hpack(__float2half(t.z * e.z), __float2half(t.w * e.w)));
    uint2 tf = make_uint2(hpack(__float2half(t.x), __float2half(t.y)),
                          hpack(__float2half(t.z), __float2half(t.w)));
    *(uint2*)(g_Gf + base) = gf;
    *(uint2*)(g_Tf + base) = tf;
}

// ---------------------------------------------------------------------------
// Kernel 1c: Hvf = fp16(H_v) elementwise
// ---------------------------------------------------------------------------
__global__ __launch_bounds__(256)
void convert_hv_kernel(const float* __restrict__ Hv) {
    unsigned g = blockIdx.x * 256u + threadIdx.x;
    size_t base = (size_t)g * 4;
    float4 v = *(const float4*)(Hv + base);
    *(uint2*)(g_Hvf + base) = make_uint2(hpack(__float2half(v.x), __float2half(v.y)),
                                         hpack(__float2half(v.z), __float2half(v.w)));
}

// ---------------------------------------------------------------------------
// Kernel 1d: WT hi/lo = transposed split of W  ([n][k] = W[k][n])
// ---------------------------------------------------------------------------
__global__ __launch_bounds__(256)
void convert_wt_kernel(const float* __restrict__ W) {
    __shared__ float tile[32][33];
    int tx = threadIdx.x & 31;
    int ty = threadIdx.x >> 5;
    int n0 = blockIdx.x * 32;
    int k0 = blockIdx.y * 32;
#pragma unroll
    for (int i = ty; i < 32; i += 8)
        tile[i][tx] = W[(size_t)(k0 + i) * OUT_V + n0 + tx];
    __syncthreads();
#pragma unroll
    for (int i = ty; i < 32; i += 8) {
        __half h, l;
        hsplit(tile[tx][i], h, l);
        size_t idx = (size_t)(n0 + i) * IN_V + k0 + tx;
        g_WThi[idx] = h;
        g_WTlo[idx] = l;
    }
}

// ---------------------------------------------------------------------------
// Kernel 2: HvWT[n][j] = sum_k W[k][n]*Hv[j][k]   (A = WT split, B = Hvf)
// 128x128 tile, 2-product.  M=512 (n), N=4096 (j), K=512.
// ---------------------------------------------------------------------------
__global__ __launch_bounds__(256, 1)
void hvw_mma() {
    extern __shared__ char smem[];
    uint32_t sb = smem_u32(smem);
    const int tid  = threadIdx.x;
    const int wid  = tid >> 5;
    const int lane = tid & 31;
    const int wr = wid >> 2, wc = wid & 3;

    const unsigned rowbase = blockIdx.y * 128u;   // n
    const unsigned colbase = blockIdx.x * 128u;   // j

    float acc[4][4][4];
#pragma unroll
    for (int m = 0; m < 4; m++)
#pragma unroll
        for (int n = 0; n < 4; n++)
#pragma unroll
            for (int i = 0; i < 4; i++) acc[m][n][i] = 0.f;

    auto load_chunk = [&](int c, int s) {
        uint32_t sbase = sb + (uint32_t)s * H_STAGE;
        unsigned kbase = (unsigned)c * KC;
#pragma unroll
        for (int i = 0; i < 12; i++) {
            const int arr = i >> 2;
            const int ci  = (i & 3) * 256 + tid;
            const int r   = ci >> 3;
            const int q   = ci & 7;
            const __half* src;
            unsigned grow;
            if (arr == 0)      { src = g_WThi; grow = rowbase + r; }
            else if (arr == 1) { src = g_WTlo; grow = rowbase + r; }
            else               { src = g_Hvf;  grow = colbase + r; }
            cpa16(sbase + (uint32_t)arr * 16384u + swz((uint32_t)(r * 128 + q * 16)),
                  (const void*)(src + (size_t)grow * IN_V + kbase + q * 8));
        }
    };

    load_chunk(0, 0); CP_COMMIT();
    load_chunk(1, 1); CP_COMMIT();

    const int la_row = lane & 15, la_kh = lane >> 4;
    const int gB = lane >> 3, rB = lane & 7, ntO = gB >> 1, khB = gB & 1;

    for (int c = 0; c < NCHUNKH; c++) {
        CP_WAIT1();
        __syncthreads();
        if (c + 2 < NCHUNKH) load_chunk(c + 2, (c + 2) % 3);
        CP_COMMIT();
        uint32_t stage = sb + (uint32_t)(c % 3) * H_STAGE;
        uint32_t aHiB = stage, aLoB = stage + 16384u, bB = stage + 32768u;
#pragma unroll
        for (int ks = 0; ks < 4; ks++) {
            uint32_t ahi[4][4], alo[4][4], bf[4][2];
#pragma unroll
            for (int mt = 0; mt < 4; mt++) {
                uint32_t off = swz((uint32_t)((wr * 64 + mt * 16 + la_row) * 128
                                              + ks * 32 + la_kh * 16));
                ldsm_x4(ahi[mt][0], ahi[mt][1], ahi[mt][2], ahi[mt][3], aHiB + off);
                ldsm_x4(alo[mt][0], alo[mt][1], alo[mt][2], alo[mt][3], aLoB + off);
            }
#pragma unroll
            for (int p = 0; p < 2; p++) {
                uint32_t off = swz((uint32_t)((wc * 32 + (p * 2 + ntO) * 8 + rB) * 128
                                              + ks * 32 + khB * 16));
                ldsm_x4(bf[p * 2][0], bf[p * 2][1], bf[p * 2 + 1][0], bf[p * 2 + 1][1],
                        bB + off);
            }
#pragma unroll
            for (int mt = 0; mt < 4; mt++)
#pragma unroll
                for (int nt = 0; nt < 4; nt++) {
                    mma_f16(acc[mt][nt], ahi[mt], bf[nt]);
                    mma_f16(acc[mt][nt], alo[mt], bf[nt]);
                }
        }
    }

#pragma unroll
    for (int mt = 0; mt < 4; mt++) {
        unsigned r0 = rowbase + wr * 64 + mt * 16 + (lane >> 2);
#pragma unroll
        for (int nt = 0; nt < 4; nt++) {
            unsigned cc = colbase + wc * 32 + nt * 8 + 2 * (lane & 3);
            *(uint32_t*)&g_HvWT[(size_t)r0 * N_NODES + cc] =
                hpack(__float2half(acc[mt][nt][0]), __float2half(acc[mt][nt][1]));
            *(uint32_t*)&g_HvWT[(size_t)(r0 + 8) * N_NODES + cc] =
                hpack(__float2half(acc[mt][nt][2]), __float2half(acc[mt][nt][3]));
        }
    }
}

// ---------------------------------------------------------------------------
// Kernel 3: gemm1 = lower-tri 256x128 tiles of M1 = Gf @ Tf^T (single product)
// 8 warps 4x2, warp tile 64x64.  Epilogue: Bcomb fp16, smem-staged coalesced.
// ---------------------------------------------------------------------------
__global__ __launch_bounds__(256, 1)
void gemm1_mma(const float* __restrict__ adj_v) {
    extern __shared__ char smem[];
    uint32_t sb = smem_u32(smem);
    const int tid  = threadIdx.x;
    const int wid  = tid >> 5;
    const int lane = tid & 31;
    const int wr   = wid >> 1;        // 0..3
    const int wc   = wid & 1;         // 0..1

    unsigned l = blockIdx.x;
    unsigned rt = (unsigned)((sqrtf(4.f * (float)l + 1.f) - 1.f) * 0.5f);
    while (rt * rt + rt > l) rt--;
    while ((rt + 1u) * (rt + 1u) + (rt + 1u) <= l) rt++;
    unsigned ct = l - (rt * rt + rt);
    const unsigned rowbase = rt * 256u;
    const unsigned colbase = ct * 128u;
    const bool crossing = (ct >= 2u * rt);

    float acc[4][8][4];
#pragma unroll
    for (int m = 0; m < 4; m++)
#pragma unroll
        for (int n = 0; n < 8; n++)
#pragma unroll
            for (int i = 0; i < 4; i++) acc[m][n][i] = 0.f;

    auto load_chunk = [&](int c, int s) {
        uint32_t sbase = sb + (uint32_t)s * G1_STAGE;
        unsigned kbase = (unsigned)c * KC;
#pragma unroll
        for (int i = 0; i < 8; i++) {              // A (Gf): 256 rows
            int slot = i * 256 + tid;
            int r = slot >> 3, q = slot & 7;
            cpa16(sbase + swz((uint32_t)(r * 128 + q * 16)),
                  (const void*)(g_Gf + (size_t)(rowbase + r) * E_EDGES + kbase + q * 8));
        }
#pragma unroll
        for (int i = 0; i < 4; i++) {              // B (Tf): 128 rows
            int slot = i * 256 + tid;
            int r = slot >> 3, q = slot & 7;
            cpa16(sbase + 32768u + swz((uint32_t)(r * 128 + q * 16)),
                  (const void*)(g_Tf + (size_t)(colbase + r) * E_EDGES + kbase + q * 8));
        }
    };

    load_chunk(0, 0); CP_COMMIT();
    load_chunk(1, 1); CP_COMMIT();

    const int la_row = lane & 15, la_kh = lane >> 4;
    const int gB = lane >> 3, rB = lane & 7, ntO = gB >> 1, khB = gB & 1;

    for (int c = 0; c < NCHUNK1; c++) {
        CP_WAIT1();
        __syncthreads();
        if (c + 2 < NCHUNK1) load_chunk(c + 2, (c + 2) % 3);
        CP_COMMIT();
        uint32_t stage = sb + (uint32_t)(c % 3) * G1_STAGE;
        uint32_t aB = stage, bB = stage + 32768u;
#pragma unroll
        for (int ks = 0; ks < 4; ks++) {
            uint32_t af[4][4], bf[8][2];
#pragma unroll
            for (int mt = 0; mt < 4; mt++) {
                uint32_t off = swz((uint32_t)((wr * 64 + mt * 16 + la_row) * 128
                                              + ks * 32 + la_kh * 16));
                ldsm_x4(af[mt][0], af[mt][1], af[mt][2], af[mt][3], aB + off);
            }
#pragma unroll
            for (int p = 0; p < 4; p++) {
                uint32_t off = swz((uint32_t)((wc * 64 + (p * 2 + ntO) * 8 + rB) * 128
                                              + ks * 32 + khB * 16));
                ldsm_x4(bf[p * 2][0], bf[p * 2][1], bf[p * 2 + 1][0], bf[p * 2 + 1][1],
                        bB + off);
            }
#pragma unroll
            for (int mt = 0; mt < 4; mt++)
#pragma unroll
                for (int nt = 0; nt < 8; nt++)
                    mma_f16(acc[mt][nt], af[mt], bf[nt]);
        }
    }
    __syncthreads();   // smem about to be reused by the epilogue

    if (!crossing) {
        // -------- Phase 1: direct tile, staged -> coalesced STG --------
        // smem: Dhi rows stride 272B (136 halves), 256 rows = 69632B
#pragma unroll
        for (int mt = 0; mt < 4; mt++) {
            int rl0 = wr * 64 + mt * 16 + (lane >> 2);
            int rl1 = rl0 + 8;
            unsigned r0 = rowbase + rl0, r1 = rowbase + rl1;
#pragma unroll
            for (int nt = 0; nt < 8; nt++) {
                int cl = wc * 64 + nt * 8 + 2 * (lane & 3);
                unsigned cc = colbase + cl;
                float2 a0 = *(const float2*)&adj_v[(size_t)r0 * N_NODES + cc];
                float2 a1 = *(const float2*)&adj_v[(size_t)r1 * N_NODES + cc];
                *(uint32_t*)(smem + rl0 * 272 + cl * 2) =
                    hpack(__float2half(0.5f * (acc[mt][nt][0] + 1.f) * a0.x),
                          __float2half(0.5f * (acc[mt][nt][1] + 1.f) * a0.y));
                *(uint32_t*)(smem + rl1 * 272 + cl * 2) =
                    hpack(__float2half(0.5f * (acc[mt][nt][2] + 1.f) * a1.x),
                          __float2half(0.5f * (acc[mt][nt][3] + 1.f) * a1.y));
            }
        }
        __syncthreads();
#pragma unroll
        for (int it = 0; it < 16; it++) {
            int slot = it * 256 + tid;
            int r = slot >> 4, q = slot & 15;
            uint4 v = *(uint4*)(smem + r * 272 + q * 16);
            *(uint4*)&g_Bf[(size_t)(rowbase + r) * N_NODES + colbase + q * 8] = v;
        }
        __syncthreads();

        // -------- Phase 2: mirror, two 128-row halves --------
#pragma unroll
        for (int h = 0; h < 2; h++) {
            // coop load adjM[cl][rl] = adj_v[colbase+cl][rowbase+128h+rl]
#pragma unroll
            for (int it = 0; it < 16; it++) {
                int slot = it * 256 + tid;
                int cl = slot >> 5, q = slot & 31;
                float4 v = *(const float4*)&adj_v[(size_t)(colbase + cl) * N_NODES
                                                  + rowbase + h * 128 + q * 4];
                *(float4*)(smem + cl * 528 + q * 16) = v;
            }
            __syncthreads();
            if ((wr >> 1) == h) {
#pragma unroll
                for (int mt = 0; mt < 4; mt++)
#pragma unroll
                    for (int nt = 0; nt < 8; nt++)
#pragma unroll
                        for (int e = 0; e < 4; e++) {
                            int rl = (wr & 1) * 64 + mt * 16 + (lane >> 2) + (e >> 1) * 8;
                            int cl = wc * 64 + nt * 8 + 2 * (lane & 3) + (e & 1);
                            float adjv = *(float*)(smem + cl * 528 + rl * 4);
                            *(__half*)(smem + 67584 + cl * 272 + rl * 2) =
                                __float2half(0.5f * (acc[mt][nt][e] + 1.f) * adjv);
                        }
            }
            __syncthreads();
#pragma unroll
            for (int it = 0; it < 8; it++) {
                int slot = it * 256 + tid;
                int cl = slot >> 4, q = slot & 15;
                uint4 v = *(uint4*)(smem + 67584 + cl * 272 + q * 16);
                *(uint4*)&g_Bf[(size_t)(colbase + cl) * N_NODES
                               + rowbase + h * 128 + q * 8] = v;
            }
            __syncthreads();
        }
    } else {
        // crossing tiles: predicated scalar path (writes each element once)
#pragma unroll
        for (int mt = 0; mt < 4; mt++) {
            unsigned r0 = rowbase + wr * 64 + mt * 16 + (lane >> 2);
#pragma unroll
            for (int nt = 0; nt < 8; nt++) {
                unsigned cc = colbase + wc * 64 + nt * 8 + 2 * (lane & 3);
#pragma unroll
                for (int e = 0; e < 4; e++) {
                    unsigned r = r0 + (e >> 1) * 8;
                    unsigned c2 = cc + (e & 1);
                    float a = acc[mt][nt][e];
                    if (r >= c2) {
                        float av = adj_v[(size_t)r * N_NODES + c2];
                        float bv = (r == c2) ? av : 0.5f * (a + 1.f) * av;
                        g_Bf[(size_t)r * N_NODES + c2] = __float2half(bv);
                    }
                    if (r > c2) {
                        float bm = 0.5f * (a + 1.f) * adj_v[(size_t)c2 * N_NODES + r];
                        g_Bf[(size_t)c2 * N_NODES + r] = __float2half(bm);
                    }
                }
            }
        }
    }
}

// ---------------------------------------------------------------------------
// Kernel 4: ret = Bf @ HvWT^T + bias  (single product).  M=4096,N=512,K=4096.
// A = g_Bf [i][j], B = g_HvWT [n][j]  (both K-major, stride N_NODES).
// ---------------------------------------------------------------------------
__global__ __launch_bounds__(256, 1)
void final_mma(const float* __restrict__ bias, float* __restrict__ out) {
    extern __shared__ char smem[];
    uint32_t sb = smem_u32(smem);
    const int tid  = threadIdx.x;
    const int wid  = tid >> 5;
    const int lane = tid & 31;
    const int wr = wid >> 2, wc = wid & 3;

    const unsigned rowbase = blockIdx.y * 128u;   // i
    const unsigned colbase = blockIdx.x * 128u;   // n

    float acc[4][4][4];
#pragma unroll
    for (int m = 0; m < 4; m++)
#pragma unroll
        for (int n = 0; n < 4; n++)
#pragma unroll
            for (int i = 0; i < 4; i++) acc[m][n][i] = 0.f;

    auto load_chunk = [&](int c, int s) {
        uint32_t sbase = sb + (uint32_t)s * F_STAGE;
        unsigned kbase = (unsigned)c * KC;
#pragma unroll
        for (int i = 0; i < 8; i++) {
            const int arr = i >> 2;                 // 0:A 1:B
            const int ci  = (i & 3) * 256 + tid;
            const int r   = ci >> 3;
            const int q   = ci & 7;
            const __half* src = (arr == 0) ? g_Bf : g_HvWT;
            unsigned grow = (arr == 0) ? (rowbase + r) : (colbase + r);
            cpa16(sbase + (uint32_t)arr * 16384u + swz((uint32_t)(r * 128 + q * 16)),
                  (const void*)(src + (size_t)grow * N_NODES + kbase + q * 8));
        }
    };

    load_chunk(0, 0); CP_COMMIT();
    load_chunk(1, 1); CP_COMMIT();
    load_chunk(2, 2); CP_COMMIT();

    const int la_row = lane & 15, la_kh = lane >> 4;
    const int gB = lane >> 3, rB = lane & 7, ntO = gB >> 1, khB = gB & 1;

    for (int c = 0; c < NCHUNKF; c++) {
        CP_WAIT2();
        __syncthreads();
        if (c + 3 < NCHUNKF) load_chunk(c + 3, (c + 3) & 3);
        CP_COMMIT();
        uint32_t stage = sb + (uint32_t)(c & 3) * F_STAGE;
        uint32_t aB = stage, bB = stage + 16384u;
#pragma unroll
        for (int ks = 0; ks < 4; ks++) {
            uint32_t af[4][4], bf[4][2];
#pragma unroll
            for (int mt = 0; mt < 4; mt++) {
                uint32_t off = swz((uint32_t)((wr * 64 + mt * 16 + la_row) * 128
                                              + ks * 32 + la_kh * 16));
                ldsm_x4(af[mt][0], af[mt][1], af[mt][2], af[mt][3], aB + off);
            }
#pragma unroll
            for (int p = 0; p < 2; p++) {
                uint32_t off = swz((uint32_t)((wc * 32 + (p * 2 + ntO) * 8 + rB) * 128
                                              + ks * 32 + khB * 16));
                ldsm_x4(bf[p * 2][0], bf[p * 2][1], bf[p * 2 + 1][0], bf[p * 2 + 1][1],
                        bB + off);
            }
#pragma unroll
            for (int mt = 0; mt < 4; mt++)
#pragma unroll
                for (int nt = 0; nt < 4; nt++)
                    mma_f16(acc[mt][nt], af[mt], bf[nt]);
        }
    }

#pragma unroll
    for (int mt = 0; mt < 4; mt++) {
        unsigned r0 = rowbase + wr * 64 + mt * 16 + (lane >> 2);
#pragma unroll
        for (int nt = 0; nt < 4; nt++) {
            unsigned cc = colbase + wc * 32 + nt * 8 + 2 * (lane & 3);
            float2 bv = *(const float2*)&bias[cc];
            *(float2*)&out[(size_t)r0 * OUT_V + cc] =
                make_float2(acc[mt][nt][0] + bv.x, acc[mt][nt][1] + bv.y);
            *(float2*)&out[(size_t)(r0 + 8) * OUT_V + cc] =
                make_float2(acc[mt][nt][2] + bv.x, acc[mt][nt][3] + bv.y);
        }
    }
}

// ---------------------------------------------------------------------------
extern "C" void kernel_launch(void* const* d_in, const int* in_sizes, int n_in,
                              void* d_out, int out_size) {
    const float* H_v   = (const float*)d_in[0];
    const float* H_e   = (const float*)d_in[1];
    // d_in[2] = adj_e : unused by the reference
    const float* adj_v = (const float*)d_in[3];
    const float* T     = (const float*)d_in[4];
    const float* W     = (const float*)d_in[5];
    const float* p     = (const float*)d_in[6];
    const float* bias  = (const float*)d_in[7];
    float* out = (float*)d_out;

    static bool attr_done = false;
    if (!attr_done) {
        cudaFuncSetAttribute(gemm1_mma, cudaFuncAttributeMaxDynamicSharedMemorySize, G1_SMEM);
        cudaFuncSetAttribute(hvw_mma,   cudaFuncAttributeMaxDynamicSharedMemorySize, H_SMEM);
        cudaFuncSetAttribute(final_mma, cudaFuncAttributeMaxDynamicSharedMemorySize, F_SMEM);
        attr_done = true;
    }

    // 1. e = H_e @ p^T
    escale_kernel<<<E_EDGES / 8, 256>>>(H_e, p);

    // 1b-1d. fp16 conversions
    convert_kernel<<<(N_NODES * (E_EDGES / 4)) / 256, 256>>>(T);
    convert_hv_kernel<<<(N_NODES * (IN_V / 4)) / 256, 256>>>(H_v);
    convert_wt_kernel<<<dim3(OUT_V / 32, IN_V / 32), 256>>>(W);

    // 2. HvWT = (W^T split) @ Hv^T
    hvw_mma<<<dim3(N_NODES / 128, OUT_V / 128), 256, H_SMEM>>>();

    // 3. lower-tri M1 tiles + fused Bcomb fp16 epilogue (staged)
    gemm1_mma<<<NTILE1, 256, G1_SMEM>>>(adj_v);

    // 4. ret = Bf @ HvWT^T + bias
    final_mma<<<dim3(OUT_V / 128, N_NODES / 128), 256, F_SMEM>>>(bias, out);

    // 5. second output: H_e passthrough
    int he_elems = in_sizes[1];
    cudaMemcpyAsync(out + ((size_t)out_size - he_elems), H_e,
                    (size_t)he_elems * sizeof(float),
                    cudaMemcpyDeviceToDevice, 0);
}

// round 11
// speedup vs baseline: 2.5446x; 1.0427x over previous
#include <cuda_runtime.h>
#include <cuda_fp16.h>
#include <cstdint>
#include <cstddef>

// ---------------------------------------------------------------------------
// GraphConvolution (base sm_103, mma.sync HMMA):
//   e     = H_e @ p^T
//   M1    = (T*diag(e)) @ T^T        lower-tri 256x128 tiles, single-fp16 MMA
//   Bcomb = 0.5*(M1'+1) .* adj_v     fused epilogue -> single fp16, smem-staged
//   HvWT  = (W^T split) @ H_v^T      fp16 2-product (W exact), [OUT_V][N]
//   ret   = Bcomb @ HvWT^T + bias    single-product fp16 mma -> out
//   out   = concat(ret, H_e)
// Side chain {convert_hv, convert_wt, hvw, memcpy} forked to stream s1,
// overlapping the critical chain {escale -> convert -> gemm1} on stream 0.
// ---------------------------------------------------------------------------

#define N_NODES 4096
#define E_EDGES 8192
#define IN_V    512
#define OUT_V   512
#define IN_E    128

#define KC1     128
#define NCHUNK1 (E_EDGES / KC1)   // 64
#define KC      64
#define NCHUNKF (N_NODES / KC)    // 64
#define NCHUNKH (IN_V / KC)       // 8
#define NTILE1  272               // lower-tri 256x128 tiles

// gemm1 stage: A(Gf 256x128 = 64K as two 32K sub-tiles) + B(Tf 128x128 = 32K
// as two 16K sub-tiles) = 96K, 2 stages
#define G1_STAGE  98304
#define G1_SMEM   (2 * G1_STAGE)      // 196608 (epilogue needs 102400)
// hvw: 2-product stage = 48K x 3
#define H_STAGE   49152
#define H_SMEM    (3 * H_STAGE)
// final: single-product stage = 32K x 4
#define F_STAGE   32768
#define F_SMEM    (4 * F_STAGE)

// Static device scratch
__device__ float g_escale[E_EDGES];
__device__ __half g_Gf [(size_t)N_NODES * E_EDGES];   // 64 MB
__device__ __half g_Tf [(size_t)N_NODES * E_EDGES];   // 64 MB
__device__ __half g_Bf [(size_t)N_NODES * N_NODES];   // 32 MB
__device__ __half g_Hvf[(size_t)N_NODES * IN_V];      // 4 MB
__device__ __half g_WThi[(size_t)OUT_V * IN_V];
__device__ __half g_WTlo[(size_t)OUT_V * IN_V];
__device__ __half g_HvWT[(size_t)OUT_V * N_NODES];    // 4 MB, [n][j]

// ------------------------------ helpers ------------------------------------
__device__ __forceinline__ uint32_t smem_u32(const void* p) {
    uint32_t a;
    asm("{ .reg .u64 t; cvta.to.shared.u64 t, %1; cvt.u32.u64 %0, t; }"
        : "=r"(a) : "l"(p));
    return a;
}
__device__ __forceinline__ uint32_t swz(uint32_t x) { return x ^ ((x >> 3) & 0x70u); }

__device__ __forceinline__ void ldsm_x4(uint32_t& a0, uint32_t& a1,
                                        uint32_t& a2, uint32_t& a3, uint32_t addr) {
    asm volatile("ldmatrix.sync.aligned.m8n8.x4.shared.b16 {%0,%1,%2,%3}, [%4];"
                 : "=r"(a0), "=r"(a1), "=r"(a2), "=r"(a3) : "r"(addr));
}
__device__ __forceinline__ void mma_f16(float* d, const uint32_t* a, const uint32_t* b) {
    asm volatile(
        "mma.sync.aligned.m16n8k16.row.col.f32.f16.f16.f32 "
        "{%0,%1,%2,%3}, {%4,%5,%6,%7}, {%8,%9}, {%0,%1,%2,%3};"
        : "+f"(d[0]), "+f"(d[1]), "+f"(d[2]), "+f"(d[3])
        : "r"(a[0]), "r"(a[1]), "r"(a[2]), "r"(a[3]), "r"(b[0]), "r"(b[1]));
}
__device__ __forceinline__ void hsplit(float v, __half& h, __half& l) {
    h = __float2half(v);
    l = __float2half(v - __half2float(h));
}
__device__ __forceinline__ uint32_t hpack(__half a, __half b) {
    return (uint32_t)__half_as_ushort(a) | ((uint32_t)__half_as_ushort(b) << 16);
}
__device__ __forceinline__ void cpa16(uint32_t dst, const void* src) {
    asm volatile("cp.async.cg.shared.global [%0], [%1], 16;" :: "r"(dst), "l"(src));
}
#define CP_COMMIT() asm volatile("cp.async.commit_group;" ::: "memory")
#define CP_WAIT0()  asm volatile("cp.async.wait_group 0;" ::: "memory")
#define CP_WAIT1()  asm volatile("cp.async.wait_group 1;" ::: "memory")
#define CP_WAIT2()  asm volatile("cp.async.wait_group 2;" ::: "memory")

// ---------------------------------------------------------------------------
// Kernel 1: e[r] = dot(H_e[r,:], p)
// ---------------------------------------------------------------------------
__global__ void escale_kernel(const float* __restrict__ He,
                              const float* __restrict__ p) {
    int warp = threadIdx.x >> 5;
    int lane = threadIdx.x & 31;
    int row  = blockIdx.x * 8 + warp;
    if (row >= E_EDGES) return;
    const float* hr = He + (size_t)row * IN_E;
    float s = 0.f;
#pragma unroll
    for (int i = 0; i < IN_E; i += 32)
        s += hr[i + lane] * p[i + lane];
#pragma unroll
    for (int off = 16; off > 0; off >>= 1)
        s += __shfl_down_sync(0xffffffffu, s, off);
    if (lane == 0) g_escale[row] = s;
}

// ---------------------------------------------------------------------------
// Kernel 1b: Gf = fp16(T*diag(e)); Tf = fp16(T)
// ---------------------------------------------------------------------------
__global__ __launch_bounds__(256)
void convert_kernel(const float* __restrict__ T) {
    unsigned g   = blockIdx.x * 256u + threadIdx.x;
    unsigned row = g >> 11;
    unsigned k4  = (g & 2047u) * 4u;
    size_t base = (size_t)row * E_EDGES + k4;
    float4 t = *(const float4*)(T + base);
    float4 e = *(const float4*)(g_escale + k4);
    uint2 gf = make_uint2(hpack(__float2half(t.x * e.x), __float2half(t.y * e.y)),
                          hpack(__float2half(t.z * e.z), __float2half(t.w * e.w)));
    uint2 tf = make_uint2(hpack(__float2half(t.x), __float2half(t.y)),
                          hpack(__float2half(t.z), __float2half(t.w)));
    *(uint2*)(g_Gf + base) = gf;
    *(uint2*)(g_Tf + base) = tf;
}

// ---------------------------------------------------------------------------
// Kernel 1c: Hvf = fp16(H_v) elementwise
// ---------------------------------------------------------------------------
__global__ __launch_bounds__(256)
void convert_hv_kernel(const float* __restrict__ Hv) {
    unsigned g = blockIdx.x * 256u + threadIdx.x;
    size_t base = (size_t)g * 4;
    float4 v = *(const float4*)(Hv + base);
    *(uint2*)(g_Hvf + base) = make_uint2(hpack(__float2half(v.x), __float2half(v.y)),
                                         hpack(__float2half(v.z), __float2half(v.w)));
}

// ---------------------------------------------------------------------------
// Kernel 1d: WT hi/lo = transposed split of W  ([n][k] = W[k][n])
// ---------------------------------------------------------------------------
__global__ __launch_bounds__(256)
void convert_wt_kernel(const float* __restrict__ W) {
    __shared__ float tile[32][33];
    int tx = threadIdx.x & 31;
    int ty = threadIdx.x >> 5;
    int n0 = blockIdx.x * 32;
    int k0 = blockIdx.y * 32;
#pragma unroll
    for (int i = ty; i < 32; i += 8)
        tile[i][tx] = W[(size_t)(k0 + i) * OUT_V + n0 + tx];
    __syncthreads();
#pragma unroll
    for (int i = ty; i < 32; i += 8) {
        __half h, l;
        hsplit(tile[tx][i], h, l);
        size_t idx = (size_t)(n0 + i) * IN_V + k0 + tx;
        g_WThi[idx] = h;
        g_WTlo[idx] = l;
    }
}

// ---------------------------------------------------------------------------
// Kernel 2: HvWT[n][j] = sum_k W[k][n]*Hv[j][k]   (A = WT split, B = Hvf)
// 128x128 tile, 2-product.  M=512 (n), N=4096 (j), K=512.
// ---------------------------------------------------------------------------
__global__ __launch_bounds__(256, 1)
void hvw_mma() {
    extern __shared__ char smem[];
    uint32_t sb = smem_u32(smem);
    const int tid  = threadIdx.x;
    const int wid  = tid >> 5;
    const int lane = tid & 31;
    const int wr = wid >> 2, wc = wid & 3;

    const unsigned rowbase = blockIdx.y * 128u;   // n
    const unsigned colbase = blockIdx.x * 128u;   // j

    float acc[4][4][4];
#pragma unroll
    for (int m = 0; m < 4; m++)
#pragma unroll
        for (int n = 0; n < 4; n++)
#pragma unroll
            for (int i = 0; i < 4; i++) acc[m][n][i] = 0.f;

    auto load_chunk = [&](int c, int s) {
        uint32_t sbase = sb + (uint32_t)s * H_STAGE;
        unsigned kbase = (unsigned)c * KC;
#pragma unroll
        for (int i = 0; i < 12; i++) {
            const int arr = i >> 2;
            const int ci  = (i & 3) * 256 + tid;
            const int r   = ci >> 3;
            const int q   = ci & 7;
            const __half* src;
            unsigned grow;
            if (arr == 0)      { src = g_WThi; grow = rowbase + r; }
            else if (arr == 1) { src = g_WTlo; grow = rowbase + r; }
            else               { src = g_Hvf;  grow = colbase + r; }
            cpa16(sbase + (uint32_t)arr * 16384u + swz((uint32_t)(r * 128 + q * 16)),
                  (const void*)(src + (size_t)grow * IN_V + kbase + q * 8));
        }
    };

    load_chunk(0, 0); CP_COMMIT();
    load_chunk(1, 1); CP_COMMIT();

    const int la_row = lane & 15, la_kh = lane >> 4;
    const int gB = lane >> 3, rB = lane & 7, ntO = gB >> 1, khB = gB & 1;

    for (int c = 0; c < NCHUNKH; c++) {
        CP_WAIT1();
        __syncthreads();
        if (c + 2 < NCHUNKH) load_chunk(c + 2, (c + 2) % 3);
        CP_COMMIT();
        uint32_t stage = sb + (uint32_t)(c % 3) * H_STAGE;
        uint32_t aHiB = stage, aLoB = stage + 16384u, bB = stage + 32768u;
#pragma unroll
        for (int ks = 0; ks < 4; ks++) {
            uint32_t ahi[4][4], alo[4][4], bf[4][2];
#pragma unroll
            for (int mt = 0; mt < 4; mt++) {
                uint32_t off = swz((uint32_t)((wr * 64 + mt * 16 + la_row) * 128
                                              + ks * 32 + la_kh * 16));
                ldsm_x4(ahi[mt][0], ahi[mt][1], ahi[mt][2], ahi[mt][3], aHiB + off);
                ldsm_x4(alo[mt][0], alo[mt][1], alo[mt][2], alo[mt][3], aLoB + off);
            }
#pragma unroll
            for (int p = 0; p < 2; p++) {
                uint32_t off = swz((uint32_t)((wc * 32 + (p * 2 + ntO) * 8 + rB) * 128
                                              + ks * 32 + khB * 16));
                ldsm_x4(bf[p * 2][0], bf[p * 2][1], bf[p * 2 + 1][0], bf[p * 2 + 1][1],
                        bB + off);
            }
#pragma unroll
            for (int mt = 0; mt < 4; mt++)
#pragma unroll
                for (int nt = 0; nt < 4; nt++) {
                    mma_f16(acc[mt][nt], ahi[mt], bf[nt]);
                    mma_f16(acc[mt][nt], alo[mt], bf[nt]);
                }
        }
    }

#pragma unroll
    for (int mt = 0; mt < 4; mt++) {
        unsigned r0 = rowbase + wr * 64 + mt * 16 + (lane >> 2);
#pragma unroll
        for (int nt = 0; nt < 4; nt++) {
            unsigned cc = colbase + wc * 32 + nt * 8 + 2 * (lane & 3);
            *(uint32_t*)&g_HvWT[(size_t)r0 * N_NODES + cc] =
                hpack(__float2half(acc[mt][nt][0]), __float2half(acc[mt][nt][1]));
            *(uint32_t*)&g_HvWT[(size_t)(r0 + 8) * N_NODES + cc] =
                hpack(__float2half(acc[mt][nt][2]), __float2half(acc[mt][nt][3]));
        }
    }
}

// ---------------------------------------------------------------------------
// Kernel 3: gemm1 = lower-tri 256x128 tiles of M1 = Gf @ Tf^T (single product)
// KC1=128 (two 64-col sub-tiles per stage).  8 warps 4x2, warp tile 64x64.
// Epilogue: Bcomb fp16, smem-staged coalesced, + mirror.
// ---------------------------------------------------------------------------
__global__ __launch_bounds__(256, 1)
void gemm1_mma(const float* __restrict__ adj_v) {
    extern __shared__ char smem[];
    uint32_t sb = smem_u32(smem);
    const int tid  = threadIdx.x;
    const int wid  = tid >> 5;
    const int lane = tid & 31;
    const int wr   = wid >> 1;        // 0..3
    const int wc   = wid & 1;         // 0..1

    unsigned l = blockIdx.x;
    unsigned rt = (unsigned)((sqrtf(4.f * (float)l + 1.f) - 1.f) * 0.5f);
    while (rt * rt + rt > l) rt--;
    while ((rt + 1u) * (rt + 1u) + (rt + 1u) <= l) rt++;
    unsigned ct = l - (rt * rt + rt);
    const unsigned rowbase = rt * 256u;
    const unsigned colbase = ct * 128u;
    const bool crossing = (ct >= 2u * rt);

    float acc[4][8][4];
#pragma unroll
    for (int m = 0; m < 4; m++)
#pragma unroll
        for (int n = 0; n < 8; n++)
#pragma unroll
            for (int i = 0; i < 4; i++) acc[m][n][i] = 0.f;

    auto load_chunk = [&](int c, int s) {
        uint32_t sbase = sb + (uint32_t)s * G1_STAGE;
        unsigned kbase = (unsigned)c * KC1;
        // A (Gf): 256 rows x 128 cols as two 32K sub-tiles -> 16 slots/thread
#pragma unroll
        for (int i = 0; i < 16; i++) {
            int slot = i * 256 + tid;          // 0..4095
            int sub = slot >> 11;              // 0..1
            int w   = slot & 2047;
            int r = w >> 3, q = w & 7;
            cpa16(sbase + (uint32_t)sub * 32768u + swz((uint32_t)(r * 128 + q * 16)),
                  (const void*)(g_Gf + (size_t)(rowbase + r) * E_EDGES
                                + kbase + sub * 64 + q * 8));
        }
        // B (Tf): 128 rows x 128 cols as two 16K sub-tiles -> 8 slots/thread
#pragma unroll
        for (int i = 0; i < 8; i++) {
            int slot = i * 256 + tid;          // 0..2047
            int sub = slot >> 10;              // 0..1
            int w   = slot & 1023;
            int r = w >> 3, q = w & 7;
            cpa16(sbase + 65536u + (uint32_t)sub * 16384u
                      + swz((uint32_t)(r * 128 + q * 16)),
                  (const void*)(g_Tf + (size_t)(colbase + r) * E_EDGES
                                + kbase + sub * 64 + q * 8));
        }
    };

    load_chunk(0, 0); CP_COMMIT();

    const int la_row = lane & 15, la_kh = lane >> 4;
    const int gB = lane >> 3, rB = lane & 7, ntO = gB >> 1, khB = gB & 1;

    for (int c = 0; c < NCHUNK1; c++) {
        CP_WAIT0();
        __syncthreads();
        if (c + 1 < NCHUNK1) load_chunk(c + 1, (c + 1) & 1);
        CP_COMMIT();
        uint32_t stage = sb + (uint32_t)(c & 1) * G1_STAGE;
#pragma unroll
        for (int ks = 0; ks < 8; ks++) {
            const int sub = ks >> 2, ksl = ks & 3;
            uint32_t aB = stage + (uint32_t)sub * 32768u;
            uint32_t bB = stage + 65536u + (uint32_t)sub * 16384u;
            uint32_t af[4][4], bf[8][2];
#pragma unroll
            for (int mt = 0; mt < 4; mt++) {
                uint32_t off = swz((uint32_t)((wr * 64 + mt * 16 + la_row) * 128
                                              + ksl * 32 + la_kh * 16));
                ldsm_x4(af[mt][0], af[mt][1], af[mt][2], af[mt][3], aB + off);
            }
#pragma unroll
            for (int p = 0; p < 4; p++) {
                uint32_t off = swz((uint32_t)((wc * 64 + (p * 2 + ntO) * 8 + rB) * 128
                                              + ksl * 32 + khB * 16));
                ldsm_x4(bf[p * 2][0], bf[p * 2][1], bf[p * 2 + 1][0], bf[p * 2 + 1][1],
                        bB + off);
            }
#pragma unroll
            for (int mt = 0; mt < 4; mt++)
#pragma unroll
                for (int nt = 0; nt < 8; nt++)
                    mma_f16(acc[mt][nt], af[mt], bf[nt]);
        }
    }
    __syncthreads();   // smem about to be reused by the epilogue

    if (!crossing) {
        // -------- Phase 1: direct tile, staged -> coalesced STG --------
#pragma unroll
        for (int mt = 0; mt < 4; mt++) {
            int rl0 = wr * 64 + mt * 16 + (lane >> 2);
            int rl1 = rl0 + 8;
            unsigned r0 = rowbase + rl0, r1 = rowbase + rl1;
#pragma unroll
            for (int nt = 0; nt < 8; nt++) {
                int cl = wc * 64 + nt * 8 + 2 * (lane & 3);
                unsigned cc = colbase + cl;
                float2 a0 = *(const float2*)&adj_v[(size_t)r0 * N_NODES + cc];
                float2 a1 = *(const float2*)&adj_v[(size_t)r1 * N_NODES + cc];
                *(uint32_t*)(smem + rl0 * 272 + cl * 2) =
                    hpack(__float2half(0.5f * (acc[mt][nt][0] + 1.f) * a0.x),
                          __float2half(0.5f * (acc[mt][nt][1] + 1.f) * a0.y));
                *(uint32_t*)(smem + rl1 * 272 + cl * 2) =
                    hpack(__float2half(0.5f * (acc[mt][nt][2] + 1.f) * a1.x),
                          __float2half(0.5f * (acc[mt][nt][3] + 1.f) * a1.y));
            }
        }
        __syncthreads();
#pragma unroll
        for (int it = 0; it < 16; it++) {
            int slot = it * 256 + tid;
            int r = slot >> 4, q = slot & 15;
            uint4 v = *(uint4*)(smem + r * 272 + q * 16);
            *(uint4*)&g_Bf[(size_t)(rowbase + r) * N_NODES + colbase + q * 8] = v;
        }
        __syncthreads();

        // -------- Phase 2: mirror, two 128-row halves --------
#pragma unroll
        for (int h = 0; h < 2; h++) {
#pragma unroll
            for (int it = 0; it < 16; it++) {
                int slot = it * 256 + tid;
                int cl = slot >> 5, q = slot & 31;
                float4 v = *(const float4*)&adj_v[(size_t)(colbase + cl) * N_NODES
                                                  + rowbase + h * 128 + q * 4];
                *(float4*)(smem + cl * 528 + q * 16) = v;
            }
            __syncthreads();
            if ((wr >> 1) == h) {
#pragma unroll
                for (int mt = 0; mt < 4; mt++)
#pragma unroll
                    for (int nt = 0; nt < 8; nt++)
#pragma unroll
                        for (int e = 0; e < 4; e++) {
                            int rl = (wr & 1) * 64 + mt * 16 + (lane >> 2) + (e >> 1) * 8;
                            int cl = wc * 64 + nt * 8 + 2 * (lane & 3) + (e & 1);
                            float adjv = *(float*)(smem + cl * 528 + rl * 4);
                            *(__half*)(smem + 67584 + cl * 272 + rl * 2) =
                                __float2half(0.5f * (acc[mt][nt][e] + 1.f) * adjv);
                        }
            }
            __syncthreads();
#pragma unroll
            for (int it = 0; it < 8; it++) {
                int slot = it * 256 + tid;
                int cl = slot >> 4, q = slot & 15;
                uint4 v = *(uint4*)(smem + 67584 + cl * 272 + q * 16);
                *(uint4*)&g_Bf[(size_t)(colbase + cl) * N_NODES
                               + rowbase + h * 128 + q * 8] = v;
            }
            __syncthreads();
        }
    } else {
        // crossing tiles: predicated scalar path (writes each element once)
#pragma unroll
        for (int mt = 0; mt < 4; mt++) {
            unsigned r0 = rowbase + wr * 64 + mt * 16 + (lane >> 2);
#pragma unroll
            for (int nt = 0; nt < 8; nt++) {
                unsigned cc = colbase + wc * 64 + nt * 8 + 2 * (lane & 3);
#pragma unroll
                for (int e = 0; e < 4; e++) {
                    unsigned r = r0 + (e >> 1) * 8;
                    unsigned c2 = cc + (e & 1);
                    float a = acc[mt][nt][e];
                    if (r >= c2) {
                        float av = adj_v[(size_t)r * N_NODES + c2];
                        float bv = (r == c2) ? av : 0.5f * (a + 1.f) * av;
                        g_Bf[(size_t)r * N_NODES + c2] = __float2half(bv);
                    }
                    if (r > c2) {
                        float bm = 0.5f * (a + 1.f) * adj_v[(size_t)c2 * N_NODES + r];
                        g_Bf[(size_t)c2 * N_NODES + r] = __float2half(bm);
                    }
                }
            }
        }
    }
}

// ---------------------------------------------------------------------------
// Kernel 4: ret = Bf @ HvWT^T + bias  (single product).  M=4096,N=512,K=4096.
// ---------------------------------------------------------------------------
__global__ __launch_bounds__(256, 1)
void final_mma(const float* __restrict__ bias, float* __restrict__ out) {
    extern __shared__ char smem[];
    uint32_t sb = smem_u32(smem);
    const int tid  = threadIdx.x;
    const int wid  = tid >> 5;
    const int lane = tid & 31;
    const int wr = wid >> 2, wc = wid & 3;

    const unsigned rowbase = blockIdx.y * 128u;   // i
    const unsigned colbase = blockIdx.x * 128u;   // n

    float acc[4][4][4];
#pragma unroll
    for (int m = 0; m < 4; m++)
#pragma unroll
        for (int n = 0; n < 4; n++)
#pragma unroll
            for (int i = 0; i < 4; i++) acc[m][n][i] = 0.f;

    auto load_chunk = [&](int c, int s) {
        uint32_t sbase = sb + (uint32_t)s * F_STAGE;
        unsigned kbase = (unsigned)c * KC;
#pragma unroll
        for (int i = 0; i < 8; i++) {
            const int arr = i >> 2;                 // 0:A 1:B
            const int ci  = (i & 3) * 256 + tid;
            const int r   = ci >> 3;
            const int q   = ci & 7;
            const __half* src = (arr == 0) ? g_Bf : g_HvWT;
            unsigned grow = (arr == 0) ? (rowbase + r) : (colbase + r);
            cpa16(sbase + (uint32_t)arr * 16384u + swz((uint32_t)(r * 128 + q * 16)),
                  (const void*)(src + (size_t)grow * N_NODES + kbase + q * 8));
        }
    };

    load_chunk(0, 0); CP_COMMIT();
    load_chunk(1, 1); CP_COMMIT();
    load_chunk(2, 2); CP_COMMIT();

    const int la_row = lane & 15, la_kh = lane >> 4;
    const int gB = lane >> 3, rB = lane & 7, ntO = gB >> 1, khB = gB & 1;

    for (int c = 0; c < NCHUNKF; c++) {
        CP_WAIT2();
        __syncthreads();
        if (c + 3 < NCHUNKF) load_chunk(c + 3, (c + 3) & 3);
        CP_COMMIT();
        uint32_t stage = sb + (uint32_t)(c & 3) * F_STAGE;
        uint32_t aB = stage, bB = stage + 16384u;
#pragma unroll
        for (int ks = 0; ks < 4; ks++) {
            uint32_t af[4][4], bf[4][2];
#pragma unroll
            for (int mt = 0; mt < 4; mt++) {
                uint32_t off = swz((uint32_t)((wr * 64 + mt * 16 + la_row) * 128
                                              + ks * 32 + la_kh * 16));
                ldsm_x4(af[mt][0], af[mt][1], af[mt][2], af[mt][3], aB + off);
            }
#pragma unroll
            for (int p = 0; p < 2; p++) {
                uint32_t off = swz((uint32_t)((wc * 32 + (p * 2 + ntO) * 8 + rB) * 128
                                              + ks * 32 + khB * 16));
                ldsm_x4(bf[p * 2][0], bf[p * 2][1], bf[p * 2 + 1][0], bf[p * 2 + 1][1],
                        bB + off);
            }
#pragma unroll
            for (int mt = 0; mt < 4; mt++)
#pragma unroll
                for (int nt = 0; nt < 4; nt++)
                    mma_f16(acc[mt][nt], af[mt], bf[nt]);
        }
    }

#pragma unroll
    for (int mt = 0; mt < 4; mt++) {
        unsigned r0 = rowbase + wr * 64 + mt * 16 + (lane >> 2);
#pragma unroll
        for (int nt = 0; nt < 4; nt++) {
            unsigned cc = colbase + wc * 32 + nt * 8 + 2 * (lane & 3);
            float2 bv = *(const float2*)&bias[cc];
            *(float2*)&out[(size_t)r0 * OUT_V + cc] =
                make_float2(acc[mt][nt][0] + bv.x, acc[mt][nt][1] + bv.y);
            *(float2*)&out[(size_t)(r0 + 8) * OUT_V + cc] =
                make_float2(acc[mt][nt][2] + bv.x, acc[mt][nt][3] + bv.y);
        }
    }
}

// ---------------------------------------------------------------------------
extern "C" void kernel_launch(void* const* d_in, const int* in_sizes, int n_in,
                              void* d_out, int out_size) {
    const float* H_v   = (const float*)d_in[0];
    const float* H_e   = (const float*)d_in[1];
    // d_in[2] = adj_e : unused by the reference
    const float* adj_v = (const float*)d_in[3];
    const float* T     = (const float*)d_in[4];
    const float* W     = (const float*)d_in[5];
    const float* p     = (const float*)d_in[6];
    const float* bias  = (const float*)d_in[7];
    float* out = (float*)d_out;

    static cudaStream_t s1 = nullptr;
    static cudaEvent_t evRoot = nullptr, evJoin = nullptr;
    static bool init_done = false;
    if (!init_done) {
        cudaFuncSetAttribute(gemm1_mma, cudaFuncAttributeMaxDynamicSharedMemorySize, G1_SMEM);
        cudaFuncSetAttribute(hvw_mma,   cudaFuncAttributeMaxDynamicSharedMemorySize, H_SMEM);
        cudaFuncSetAttribute(final_mma, cudaFuncAttributeMaxDynamicSharedMemorySize, F_SMEM);
        cudaStreamCreateWithFlags(&s1, cudaStreamNonBlocking);
        cudaEventCreateWithFlags(&evRoot, cudaEventDisableTiming);
        cudaEventCreateWithFlags(&evJoin, cudaEventDisableTiming);
        init_done = true;
    }

    // Fork side chain onto s1 (rooted in the captured stream via evRoot).
    cudaEventRecord(evRoot, 0);
    cudaStreamWaitEvent(s1, evRoot, 0);

    // s1: converts for the HvW path, HvWT GEMM, and the H_e passthrough.
    convert_hv_kernel<<<(N_NODES * (IN_V / 4)) / 256, 256, 0, s1>>>(H_v);
    convert_wt_kernel<<<dim3(OUT_V / 32, IN_V / 32), 256, 0, s1>>>(W);
    hvw_mma<<<dim3(N_NODES / 128, OUT_V / 128), 256, H_SMEM, s1>>>();
    int he_elems = in_sizes[1];
    cudaMemcpyAsync(out + ((size_t)out_size - he_elems), H_e,
                    (size_t)he_elems * sizeof(float),
                    cudaMemcpyDeviceToDevice, s1);
    cudaEventRecord(evJoin, s1);

    // s0 (critical chain): e -> Gf/Tf -> gemm1 (Bcomb)
    escale_kernel<<<E_EDGES / 8, 256>>>(H_e, p);
    convert_kernel<<<(N_NODES * (E_EDGES / 4)) / 256, 256>>>(T);
    gemm1_mma<<<NTILE1, 256, G1_SMEM>>>(adj_v);

    // join, then final GEMM
    cudaStreamWaitEvent(0, evJoin, 0);
    final_mma<<<dim3(OUT_V / 128, N_NODES / 128), 256, F_SMEM>>>(bias, out);
}

// round 14
// speedup vs baseline: 2.5697x; 1.0099x over previous
#include <cuda_runtime.h>
#include <cuda_fp16.h>
#include <cstdint>
#include <cstddef>

// ---------------------------------------------------------------------------
// GraphConvolution (base sm_103, mma.sync HMMA):
//   e     = H_e @ p^T
//   M1    = (T*diag(e)) @ T^T        lower-tri 256x128 tiles, single-fp16 MMA
//   Bcomb = 0.5*(M1'+1) .* adj_v     fused epilogue -> single fp16, smem-staged
//   HvWT  = (W^T split) @ H_v^T      fp16 2-product (W exact), [OUT_V][N]
//   ret   = Bcomb @ HvWT^T + bias    single-product fp16 mma -> out
//   out   = concat(ret, H_e)
// gemm1 now runs 512 threads (16 warps, 4x4 warp grid, 64x32 warp tiles) so
// each SMSP holds 4 warps -> latency hiding across LDSM/sync/cp.async waits.
// ---------------------------------------------------------------------------

#define N_NODES 4096
#define E_EDGES 8192
#define IN_V    512
#define OUT_V   512
#define IN_E    128

#define KC      64
#define NCHUNK1 (E_EDGES / KC)    // 128
#define NCHUNKF (N_NODES / KC)    // 64
#define NCHUNKH (IN_V / KC)       // 8
#define NTILE1  272               // lower-tri 256x128 tiles

// gemm1 stage: A(Gf 256x64 = 32K) + B(Tf 128x64 = 16K) = 48K, 2 stages.
// Epilogue staging needs 102400 B -> allocate that.
#define G1_STAGE  49152
#define G1_SMEM   102400
// hvw: 2-product stage = 48K x 3
#define H_STAGE   49152
#define H_SMEM    (3 * H_STAGE)
// final: single-product stage = 32K x 4
#define F_STAGE   32768
#define F_SMEM    (4 * F_STAGE)

// Static device scratch
__device__ float g_escale[E_EDGES];
__device__ __half g_Gf [(size_t)N_NODES * E_EDGES];   // 64 MB
__device__ __half g_Tf [(size_t)N_NODES * E_EDGES];   // 64 MB
__device__ __half g_Bf [(size_t)N_NODES * N_NODES];   // 32 MB
__device__ __half g_Hvf[(size_t)N_NODES * IN_V];      // 4 MB
__device__ __half g_WThi[(size_t)OUT_V * IN_V];
__device__ __half g_WTlo[(size_t)OUT_V * IN_V];
__device__ __half g_HvWT[(size_t)OUT_V * N_NODES];    // 4 MB, [n][j]

// ------------------------------ helpers ------------------------------------
__device__ __forceinline__ uint32_t smem_u32(const void* p) {
    uint32_t a;
    asm("{ .reg .u64 t; cvta.to.shared.u64 t, %1; cvt.u32.u64 %0, t; }"
        : "=r"(a) : "l"(p));
    return a;
}
__device__ __forceinline__ uint32_t swz(uint32_t x) { return x ^ ((x >> 3) & 0x70u); }

__device__ __forceinline__ void ldsm_x4(uint32_t& a0, uint32_t& a1,
                                        uint32_t& a2, uint32_t& a3, uint32_t addr) {
    asm volatile("ldmatrix.sync.aligned.m8n8.x4.shared.b16 {%0,%1,%2,%3}, [%4];"
                 : "=r"(a0), "=r"(a1), "=r"(a2), "=r"(a3) : "r"(addr));
}
__device__ __forceinline__ void mma_f16(float* d, const uint32_t* a, const uint32_t* b) {
    asm volatile(
        "mma.sync.aligned.m16n8k16.row.col.f32.f16.f16.f32 "
        "{%0,%1,%2,%3}, {%4,%5,%6,%7}, {%8,%9}, {%0,%1,%2,%3};"
        : "+f"(d[0]), "+f"(d[1]), "+f"(d[2]), "+f"(d[3])
        : "r"(a[0]), "r"(a[1]), "r"(a[2]), "r"(a[3]), "r"(b[0]), "r"(b[1]));
}
__device__ __forceinline__ void hsplit(float v, __half& h, __half& l) {
    h = __float2half(v);
    l = __float2half(v - __half2float(h));
}
__device__ __forceinline__ uint32_t hpack(__half a, __half b) {
    return (uint32_t)__half_as_ushort(a) | ((uint32_t)__half_as_ushort(b) << 16);
}
__device__ __forceinline__ void cpa16(uint32_t dst, const void* src) {
    asm volatile("cp.async.cg.shared.global [%0], [%1], 16;" :: "r"(dst), "l"(src));
}
#define CP_COMMIT() asm volatile("cp.async.commit_group;" ::: "memory")
#define CP_WAIT0()  asm volatile("cp.async.wait_group 0;" ::: "memory")
#define CP_WAIT1()  asm volatile("cp.async.wait_group 1;" ::: "memory")
#define CP_WAIT2()  asm volatile("cp.async.wait_group 2;" ::: "memory")

// ---------------------------------------------------------------------------
// Kernel 1: e[r] = dot(H_e[r,:], p)
// ---------------------------------------------------------------------------
__global__ void escale_kernel(const float* __restrict__ He,
                              const float* __restrict__ p) {
    int warp = threadIdx.x >> 5;
    int lane = threadIdx.x & 31;
    int row  = blockIdx.x * 8 + warp;
    if (row >= E_EDGES) return;
    const float* hr = He + (size_t)row * IN_E;
    float s = 0.f;
#pragma unroll
    for (int i = 0; i < IN_E; i += 32)
        s += hr[i + lane] * p[i + lane];
#pragma unroll
    for (int off = 16; off > 0; off >>= 1)
        s += __shfl_down_sync(0xffffffffu, s, off);
    if (lane == 0) g_escale[row] = s;
}

// ---------------------------------------------------------------------------
// Kernel 1b: Gf = fp16(T*diag(e)); Tf = fp16(T)
// ---------------------------------------------------------------------------
__global__ __launch_bounds__(256)
void convert_kernel(const float* __restrict__ T) {
    unsigned g   = blockIdx.x * 256u + threadIdx.x;
    unsigned row = g >> 11;
    unsigned k4  = (g & 2047u) * 4u;
    size_t base = (size_t)row * E_EDGES + k4;
    float4 t = *(const float4*)(T + base);
    float4 e = *(const float4*)(g_escale + k4);
    uint2 gf = make_uint2(hpack(__float2half(t.x * e.x), __float2half(t.y * e.y)),
                          hpack(__float2half(t.z * e.z), __float2half(t.w * e.w)));
    uint2 tf = make_uint2(hpack(__float2half(t.x), __float2half(t.y)),
                          hpack(__float2half(t.z), __float2half(t.w)));
    *(uint2*)(g_Gf + base) = gf;
    *(uint2*)(g_Tf + base) = tf;
}

// ---------------------------------------------------------------------------
// Kernel 1c: Hvf = fp16(H_v) elementwise
// ---------------------------------------------------------------------------
__global__ __launch_bounds__(256)
void convert_hv_kernel(const float* __restrict__ Hv) {
    unsigned g = blockIdx.x * 256u + threadIdx.x;
    size_t base = (size_t)g * 4;
    float4 v = *(const float4*)(Hv + base);
    *(uint2*)(g_Hvf + base) = make_uint2(hpack(__float2half(v.x), __float2half(v.y)),
                                         hpack(__float2half(v.z), __float2half(v.w)));
}

// ---------------------------------------------------------------------------
// Kernel 1d: WT hi/lo = transposed split of W  ([n][k] = W[k][n])
// ---------------------------------------------------------------------------
__global__ __launch_bounds__(256)
void convert_wt_kernel(const float* __restrict__ W) {
    __shared__ float tile[32][33];
    int tx = threadIdx.x & 31;
    int ty = threadIdx.x >> 5;
    int n0 = blockIdx.x * 32;
    int k0 = blockIdx.y * 32;
#pragma unroll
    for (int i = ty; i < 32; i += 8)
        tile[i][tx] = W[(size_t)(k0 + i) * OUT_V + n0 + tx];
    __syncthreads();
#pragma unroll
    for (int i = ty; i < 32; i += 8) {
        __half h, l;
        hsplit(tile[tx][i], h, l);
        size_t idx = (size_t)(n0 + i) * IN_V + k0 + tx;
        g_WThi[idx] = h;
        g_WTlo[idx] = l;
    }
}

// ---------------------------------------------------------------------------
// Kernel 2: HvWT[n][j] = sum_k W[k][n]*Hv[j][k]   (A = WT split, B = Hvf)
// ---------------------------------------------------------------------------
__global__ __launch_bounds__(256, 1)
void hvw_mma() {
    extern __shared__ char smem[];
    uint32_t sb = smem_u32(smem);
    const int tid  = threadIdx.x;
    const int wid  = tid >> 5;
    const int lane = tid & 31;
    const int wr = wid >> 2, wc = wid & 3;

    const unsigned rowbase = blockIdx.y * 128u;   // n
    const unsigned colbase = blockIdx.x * 128u;   // j

    float acc[4][4][4];
#pragma unroll
    for (int m = 0; m < 4; m++)
#pragma unroll
        for (int n = 0; n < 4; n++)
#pragma unroll
            for (int i = 0; i < 4; i++) acc[m][n][i] = 0.f;

    auto load_chunk = [&](int c, int s) {
        uint32_t sbase = sb + (uint32_t)s * H_STAGE;
        unsigned kbase = (unsigned)c * KC;
#pragma unroll
        for (int i = 0; i < 12; i++) {
            const int arr = i >> 2;
            const int ci  = (i & 3) * 256 + tid;
            const int r   = ci >> 3;
            const int q   = ci & 7;
            const __half* src;
            unsigned grow;
            if (arr == 0)      { src = g_WThi; grow = rowbase + r; }
            else if (arr == 1) { src = g_WTlo; grow = rowbase + r; }
            else               { src = g_Hvf;  grow = colbase + r; }
            cpa16(sbase + (uint32_t)arr * 16384u + swz((uint32_t)(r * 128 + q * 16)),
                  (const void*)(src + (size_t)grow * IN_V + kbase + q * 8));
        }
    };

    load_chunk(0, 0); CP_COMMIT();
    load_chunk(1, 1); CP_COMMIT();

    const int la_row = lane & 15, la_kh = lane >> 4;
    const int gB = lane >> 3, rB = lane & 7, ntO = gB >> 1, khB = gB & 1;

    for (int c = 0; c < NCHUNKH; c++) {
        CP_WAIT1();
        __syncthreads();
        if (c + 2 < NCHUNKH) load_chunk(c + 2, (c + 2) % 3);
        CP_COMMIT();
        uint32_t stage = sb + (uint32_t)(c % 3) * H_STAGE;
        uint32_t aHiB = stage, aLoB = stage + 16384u, bB = stage + 32768u;
#pragma unroll
        for (int ks = 0; ks < 4; ks++) {
            uint32_t ahi[4][4], alo[4][4], bf[4][2];
#pragma unroll
            for (int mt = 0; mt < 4; mt++) {
                uint32_t off = swz((uint32_t)((wr * 64 + mt * 16 + la_row) * 128
                                              + ks * 32 + la_kh * 16));
                ldsm_x4(ahi[mt][0], ahi[mt][1], ahi[mt][2], ahi[mt][3], aHiB + off);
                ldsm_x4(alo[mt][0], alo[mt][1], alo[mt][2], alo[mt][3], aLoB + off);
            }
#pragma unroll
            for (int p = 0; p < 2; p++) {
                uint32_t off = swz((uint32_t)((wc * 32 + (p * 2 + ntO) * 8 + rB) * 128
                                              + ks * 32 + khB * 16));
                ldsm_x4(bf[p * 2][0], bf[p * 2][1], bf[p * 2 + 1][0], bf[p * 2 + 1][1],
                        bB + off);
            }
#pragma unroll
            for (int mt = 0; mt < 4; mt++)
#pragma unroll
                for (int nt = 0; nt < 4; nt++) {
                    mma_f16(acc[mt][nt], ahi[mt], bf[nt]);
                    mma_f16(acc[mt][nt], alo[mt], bf[nt]);
                }
        }
    }

#pragma unroll
    for (int mt = 0; mt < 4; mt++) {
        unsigned r0 = rowbase + wr * 64 + mt * 16 + (lane >> 2);
#pragma unroll
        for (int nt = 0; nt < 4; nt++) {
            unsigned cc = colbase + wc * 32 + nt * 8 + 2 * (lane & 3);
            *(uint32_t*)&g_HvWT[(size_t)r0 * N_NODES + cc] =
                hpack(__float2half(acc[mt][nt][0]), __float2half(acc[mt][nt][1]));
            *(uint32_t*)&g_HvWT[(size_t)(r0 + 8) * N_NODES + cc] =
                hpack(__float2half(acc[mt][nt][2]), __float2half(acc[mt][nt][3]));
        }
    }
}

// ---------------------------------------------------------------------------
// Kernel 3: gemm1 = lower-tri 256x128 tiles of M1 = Gf @ Tf^T (single product)
// 512 threads, 16 warps as 4x4, warp tile 64x32.  KC=64, 2 stages.
// Epilogue: Bcomb fp16, smem-staged coalesced, + mirror.
// ---------------------------------------------------------------------------
__global__ __launch_bounds__(512, 1)
void gemm1_mma(const float* __restrict__ adj_v) {
    extern __shared__ char smem[];
    uint32_t sb = smem_u32(smem);
    const int tid  = threadIdx.x;
    const int wid  = tid >> 5;
    const int lane = tid & 31;
    const int wr   = wid >> 2;        // 0..3 (64-row bands)
    const int wc   = wid & 3;         // 0..3 (32-col bands)

    unsigned l = blockIdx.x;
    unsigned rt = (unsigned)((sqrtf(4.f * (float)l + 1.f) - 1.f) * 0.5f);
    while (rt * rt + rt > l) rt--;
    while ((rt + 1u) * (rt + 1u) + (rt + 1u) <= l) rt++;
    unsigned ct = l - (rt * rt + rt);
    const unsigned rowbase = rt * 256u;
    const unsigned colbase = ct * 128u;
    const bool crossing = (ct >= 2u * rt);

    float acc[4][4][4];
#pragma unroll
    for (int m = 0; m < 4; m++)
#pragma unroll
        for (int n = 0; n < 4; n++)
#pragma unroll
            for (int i = 0; i < 4; i++) acc[m][n][i] = 0.f;

    auto load_chunk = [&](int c, int s) {
        uint32_t sbase = sb + (uint32_t)s * G1_STAGE;
        unsigned kbase = (unsigned)c * KC;
        // A (Gf): 256 rows x 64 cols -> 2048 16B chunks, 4 per thread
#pragma unroll
        for (int i = 0; i < 4; i++) {
            int slot = i * 512 + tid;
            int r = slot >> 3, q = slot & 7;
            cpa16(sbase + swz((uint32_t)(r * 128 + q * 16)),
                  (const void*)(g_Gf + (size_t)(rowbase + r) * E_EDGES + kbase + q * 8));
        }
        // B (Tf): 128 rows x 64 cols -> 1024 chunks, 2 per thread
#pragma unroll
        for (int i = 0; i < 2; i++) {
            int slot = i * 512 + tid;
            int r = slot >> 3, q = slot & 7;
            cpa16(sbase + 32768u + swz((uint32_t)(r * 128 + q * 16)),
                  (const void*)(g_Tf + (size_t)(colbase + r) * E_EDGES + kbase + q * 8));
        }
    };

    load_chunk(0, 0); CP_COMMIT();

    const int la_row = lane & 15, la_kh = lane >> 4;
    const int gB = lane >> 3, rB = lane & 7, ntO = gB >> 1, khB = gB & 1;

    for (int c = 0; c < NCHUNK1; c++) {
        CP_WAIT0();
        __syncthreads();
        if (c + 1 < NCHUNK1) load_chunk(c + 1, (c + 1) & 1);
        CP_COMMIT();
        uint32_t stage = sb + (uint32_t)(c & 1) * G1_STAGE;
        uint32_t aB = stage, bB = stage + 32768u;
#pragma unroll
        for (int ks = 0; ks < 4; ks++) {
            uint32_t af[4][4], bf[4][2];
#pragma unroll
            for (int mt = 0; mt < 4; mt++) {
                uint32_t off = swz((uint32_t)((wr * 64 + mt * 16 + la_row) * 128
                                              + ks * 32 + la_kh * 16));
                ldsm_x4(af[mt][0], af[mt][1], af[mt][2], af[mt][3], aB + off);
            }
#pragma unroll
            for (int p = 0; p < 2; p++) {
                uint32_t off = swz((uint32_t)((wc * 32 + (p * 2 + ntO) * 8 + rB) * 128
                                              + ks * 32 + khB * 16));
                ldsm_x4(bf[p * 2][0], bf[p * 2][1], bf[p * 2 + 1][0], bf[p * 2 + 1][1],
                        bB + off);
            }
#pragma unroll
            for (int mt = 0; mt < 4; mt++)
#pragma unroll
                for (int nt = 0; nt < 4; nt++)
                    mma_f16(acc[mt][nt], af[mt], bf[nt]);
        }
    }
    __syncthreads();   // smem about to be reused by the epilogue

    if (!crossing) {
        // -------- Phase 1: direct tile, staged -> coalesced STG --------
#pragma unroll
        for (int mt = 0; mt < 4; mt++) {
            int rl0 = wr * 64 + mt * 16 + (lane >> 2);
            int rl1 = rl0 + 8;
            unsigned r0 = rowbase + rl0, r1 = rowbase + rl1;
#pragma unroll
            for (int nt = 0; nt < 4; nt++) {
                int cl = wc * 32 + nt * 8 + 2 * (lane & 3);
                unsigned cc = colbase + cl;
                float2 a0 = *(const float2*)&adj_v[(size_t)r0 * N_NODES + cc];
                float2 a1 = *(const float2*)&adj_v[(size_t)r1 * N_NODES + cc];
                *(uint32_t*)(smem + rl0 * 272 + cl * 2) =
                    hpack(__float2half(0.5f * (acc[mt][nt][0] + 1.f) * a0.x),
                          __float2half(0.5f * (acc[mt][nt][1] + 1.f) * a0.y));
                *(uint32_t*)(smem + rl1 * 272 + cl * 2) =
                    hpack(__float2half(0.5f * (acc[mt][nt][2] + 1.f) * a1.x),
                          __float2half(0.5f * (acc[mt][nt][3] + 1.f) * a1.y));
            }
        }
        __syncthreads();
#pragma unroll
        for (int it = 0; it < 8; it++) {
            int slot = it * 512 + tid;
            int r = slot >> 4, q = slot & 15;
            uint4 v = *(uint4*)(smem + r * 272 + q * 16);
            *(uint4*)&g_Bf[(size_t)(rowbase + r) * N_NODES + colbase + q * 8] = v;
        }
        __syncthreads();

        // -------- Phase 2: mirror, two 128-row halves --------
#pragma unroll
        for (int h = 0; h < 2; h++) {
#pragma unroll
            for (int it = 0; it < 8; it++) {
                int slot = it * 512 + tid;
                int cl = slot >> 5, q = slot & 31;
                float4 v = *(const float4*)&adj_v[(size_t)(colbase + cl) * N_NODES
                                                  + rowbase + h * 128 + q * 4];
                *(float4*)(smem + cl * 528 + q * 16) = v;
            }
            __syncthreads();
            if ((wr >> 1) == h) {
#pragma unroll
                for (int mt = 0; mt < 4; mt++)
#pragma unroll
                    for (int nt = 0; nt < 4; nt++)
#pragma unroll
                        for (int e = 0; e < 4; e++) {
                            int rl = (wr & 1) * 64 + mt * 16 + (lane >> 2) + (e >> 1) * 8;
                            int cl = wc * 32 + nt * 8 + 2 * (lane & 3) + (e & 1);
                            float adjv = *(float*)(smem + cl * 528 + rl * 4);
                            *(__half*)(smem + 67584 + cl * 272 + rl * 2) =
                                __float2half(0.5f * (acc[mt][nt][e] + 1.f) * adjv);
                        }
            }
            __syncthreads();
#pragma unroll
            for (int it = 0; it < 4; it++) {
                int slot = it * 512 + tid;
                int cl = slot >> 4, q = slot & 15;
                uint4 v = *(uint4*)(smem + 67584 + cl * 272 + q * 16);
                *(uint4*)&g_Bf[(size_t)(colbase + cl) * N_NODES
                               + rowbase + h * 128 + q * 8] = v;
            }
            __syncthreads();
        }
    } else {
        // crossing tiles: predicated scalar path (writes each element once)
#pragma unroll
        for (int mt = 0; mt < 4; mt++) {
            unsigned r0 = rowbase + wr * 64 + mt * 16 + (lane >> 2);
#pragma unroll
            for (int nt = 0; nt < 4; nt++) {
                unsigned cc = colbase + wc * 32 + nt * 8 + 2 * (lane & 3);
#pragma unroll
                for (int e = 0; e < 4; e++) {
                    unsigned r = r0 + (e >> 1) * 8;
                    unsigned c2 = cc + (e & 1);
                    float a = acc[mt][nt][e];
                    if (r >= c2) {
                        float av = adj_v[(size_t)r * N_NODES + c2];
                        float bv = (r == c2) ? av : 0.5f * (a + 1.f) * av;
                        g_Bf[(size_t)r * N_NODES + c2] = __float2half(bv);
                    }
                    if (r > c2) {
                        float bm = 0.5f * (a + 1.f) * adj_v[(size_t)c2 * N_NODES + r];
                        g_Bf[(size_t)c2 * N_NODES + r] = __float2half(bm);
                    }
                }
            }
        }
    }
}

// ---------------------------------------------------------------------------
// Kernel 4: ret = Bf @ HvWT^T + bias  (single product).  M=4096,N=512,K=4096.
// ---------------------------------------------------------------------------
__global__ __launch_bounds__(256, 1)
void final_mma(const float* __restrict__ bias, float* __restrict__ out) {
    extern __shared__ char smem[];
    uint32_t sb = smem_u32(smem);
    const int tid  = threadIdx.x;
    const int wid  = tid >> 5;
    const int lane = tid & 31;
    const int wr = wid >> 2, wc = wid & 3;

    const unsigned rowbase = blockIdx.y * 128u;   // i
    const unsigned colbase = blockIdx.x * 128u;   // n

    float acc[4][4][4];
#pragma unroll
    for (int m = 0; m < 4; m++)
#pragma unroll
        for (int n = 0; n < 4; n++)
#pragma unroll
            for (int i = 0; i < 4; i++) acc[m][n][i] = 0.f;

    auto load_chunk = [&](int c, int s) {
        uint32_t sbase = sb + (uint32_t)s * F_STAGE;
        unsigned kbase = (unsigned)c * KC;
#pragma unroll
        for (int i = 0; i < 8; i++) {
            const int arr = i >> 2;                 // 0:A 1:B
            const int ci  = (i & 3) * 256 + tid;
            const int r   = ci >> 3;
            const int q   = ci & 7;
            const __half* src = (arr == 0) ? g_Bf : g_HvWT;
            unsigned grow = (arr == 0) ? (rowbase + r) : (colbase + r);
            cpa16(sbase + (uint32_t)arr * 16384u + swz((uint32_t)(r * 128 + q * 16)),
                  (const void*)(src + (size_t)grow * N_NODES + kbase + q * 8));
        }
    };

    load_chunk(0, 0); CP_COMMIT();
    load_chunk(1, 1); CP_COMMIT();
    load_chunk(2, 2); CP_COMMIT();

    const int la_row = lane & 15, la_kh = lane >> 4;
    const int gB = lane >> 3, rB = lane & 7, ntO = gB >> 1, khB = gB & 1;

    for (int c = 0; c < NCHUNKF; c++) {
        CP_WAIT2();
        __syncthreads();
        if (c + 3 < NCHUNKF) load_chunk(c + 3, (c + 3) & 3);
        CP_COMMIT();
        uint32_t stage = sb + (uint32_t)(c & 3) * F_STAGE;
        uint32_t aB = stage, bB = stage + 16384u;
#pragma unroll
        for (int ks = 0; ks < 4; ks++) {
            uint32_t af[4][4], bf[4][2];
#pragma unroll
            for (int mt = 0; mt < 4; mt++) {
                uint32_t off = swz((uint32_t)((wr * 64 + mt * 16 + la_row) * 128
                                              + ks * 32 + la_kh * 16));
                ldsm_x4(af[mt][0], af[mt][1], af[mt][2], af[mt][3], aB + off);
            }
#pragma unroll
            for (int p = 0; p < 2; p++) {
                uint32_t off = swz((uint32_t)((wc * 32 + (p * 2 + ntO) * 8 + rB) * 128
                                              + ks * 32 + khB * 16));
                ldsm_x4(bf[p * 2][0], bf[p * 2][1], bf[p * 2 + 1][0], bf[p * 2 + 1][1],
                        bB + off);
            }
#pragma unroll
            for (int mt = 0; mt < 4; mt++)
#pragma unroll
                for (int nt = 0; nt < 4; nt++)
                    mma_f16(acc[mt][nt], af[mt], bf[nt]);
        }
    }

#pragma unroll
    for (int mt = 0; mt < 4; mt++) {
        unsigned r0 = rowbase + wr * 64 + mt * 16 + (lane >> 2);
#pragma unroll
        for (int nt = 0; nt < 4; nt++) {
            unsigned cc = colbase + wc * 32 + nt * 8 + 2 * (lane & 3);
            float2 bv = *(const float2*)&bias[cc];
            *(float2*)&out[(size_t)r0 * OUT_V + cc] =
                make_float2(acc[mt][nt][0] + bv.x, acc[mt][nt][1] + bv.y);
            *(float2*)&out[(size_t)(r0 + 8) * OUT_V + cc] =
                make_float2(acc[mt][nt][2] + bv.x, acc[mt][nt][3] + bv.y);
        }
    }
}

// ---------------------------------------------------------------------------
extern "C" void kernel_launch(void* const* d_in, const int* in_sizes, int n_in,
                              void* d_out, int out_size) {
    const float* H_v   = (const float*)d_in[0];
    const float* H_e   = (const float*)d_in[1];
    // d_in[2] = adj_e : unused by the reference
    const float* adj_v = (const float*)d_in[3];
    const float* T     = (const float*)d_in[4];
    const float* W     = (const float*)d_in[5];
    const float* p     = (const float*)d_in[6];
    const float* bias  = (const float*)d_in[7];
    float* out = (float*)d_out;

    static cudaStream_t s1 = nullptr;
    static cudaEvent_t evRoot = nullptr, evJoin = nullptr;
    static bool init_done = false;
    if (!init_done) {
        cudaFuncSetAttribute(gemm1_mma, cudaFuncAttributeMaxDynamicSharedMemorySize, G1_SMEM);
        cudaFuncSetAttribute(hvw_mma,   cudaFuncAttributeMaxDynamicSharedMemorySize, H_SMEM);
        cudaFuncSetAttribute(final_mma, cudaFuncAttributeMaxDynamicSharedMemorySize, F_SMEM);
        cudaStreamCreateWithFlags(&s1, cudaStreamNonBlocking);
        cudaEventCreateWithFlags(&evRoot, cudaEventDisableTiming);
        cudaEventCreateWithFlags(&evJoin, cudaEventDisableTiming);
        init_done = true;
    }

    // Fork side chain onto s1 (rooted in the captured stream via evRoot).
    cudaEventRecord(evRoot, 0);
    cudaStreamWaitEvent(s1, evRoot, 0);

    // s1: converts for the HvW path, HvWT GEMM, and the H_e passthrough.
    convert_hv_kernel<<<(N_NODES * (IN_V / 4)) / 256, 256, 0, s1>>>(H_v);
    convert_wt_kernel<<<dim3(OUT_V / 32, IN_V / 32), 256, 0, s1>>>(W);
    hvw_mma<<<dim3(N_NODES / 128, OUT_V / 128), 256, H_SMEM, s1>>>();
    int he_elems = in_sizes[1];
    cudaMemcpyAsync(out + ((size_t)out_size - he_elems), H_e,
                    (size_t)he_elems * sizeof(float),
                    cudaMemcpyDeviceToDevice, s1);
    cudaEventRecord(evJoin, s1);

    // s0 (critical chain): e -> Gf/Tf -> gemm1 (Bcomb)
    escale_kernel<<<E_EDGES / 8, 256>>>(H_e, p);
    convert_kernel<<<(N_NODES * (E_EDGES / 4)) / 256, 256>>>(T);
    gemm1_mma<<<NTILE1, 512, G1_SMEM>>>(adj_v);

    // join, then final GEMM
    cudaStreamWaitEvent(0, evJoin, 0);
    final_mma<<<dim3(OUT_V / 128, N_NODES / 128), 256, F_SMEM>>>(bias, out);
}